// round 1
// baseline (speedup 1.0000x reference)
#include <cuda_runtime.h>
#include <math.h>

// Problem constants
#define B_  4
#define S_  2048
#define D_  1024
#define H_  16
#define DK_ 64

// Scratch: projected Q,K,V in [B,H,S,DK] layout (device globals — no allocs)
__device__ float g_Q[(size_t)B_ * H_ * S_ * DK_];
__device__ float g_K[(size_t)B_ * H_ * S_ * DK_];
__device__ float g_V[(size_t)B_ * H_ * S_ * DK_];

// ---------------------------------------------------------------------------
// Projection GEMM: out[b,h,s,dk] = X[m,:] . W[n,:] + bias[n]   (m=b*S+s, n=h*DK+dk)
// X: [8192,1024] row-major, W: [1024,1024] row-major (we need X @ W^T)
// Classic 128x128x8 smem tiling, 256 threads, 8x8 register tile.
// SCALE: pre-multiply Q by 1/sqrt(DK) = 0.125 so attention scores come out scaled.
// ---------------------------------------------------------------------------
template <bool SCALE>
__global__ __launch_bounds__(256, 2)
void proj_kernel(const float* __restrict__ X, const float* __restrict__ W,
                 const float* __restrict__ bias, float* __restrict__ out)
{
    __shared__ float As[8][128];
    __shared__ float Bs[8][128];

    const int tid = threadIdx.x;
    const int bm = blockIdx.y;      // 0..63  (M blocks)
    const int bn = blockIdx.x;      // 0..7   (N blocks)
    const int tx = tid & 15;
    const int ty = tid >> 4;
    const int lr = tid >> 1;        // load row 0..127
    const int lc = (tid & 1) * 4;   // load col 0 or 4

    const float* Aptr = X + (size_t)(bm * 128 + lr) * 1024 + lc;
    const float* Bptr = W + (size_t)(bn * 128 + lr) * 1024 + lc;

    float acc[8][8];
#pragma unroll
    for (int i = 0; i < 8; i++)
#pragma unroll
        for (int j = 0; j < 8; j++) acc[i][j] = 0.f;

    for (int k0 = 0; k0 < 1024; k0 += 8) {
        float4 a = *(const float4*)(Aptr + k0);
        float4 b = *(const float4*)(Bptr + k0);
        As[lc + 0][lr] = a.x; As[lc + 1][lr] = a.y;
        As[lc + 2][lr] = a.z; As[lc + 3][lr] = a.w;
        Bs[lc + 0][lr] = b.x; Bs[lc + 1][lr] = b.y;
        Bs[lc + 2][lr] = b.z; Bs[lc + 3][lr] = b.w;
        __syncthreads();

#pragma unroll
        for (int k = 0; k < 8; k++) {
            float4 a0 = *(const float4*)&As[k][ty * 8];
            float4 a1 = *(const float4*)&As[k][ty * 8 + 4];
            float4 b0 = *(const float4*)&Bs[k][tx * 8];
            float4 b1 = *(const float4*)&Bs[k][tx * 8 + 4];
            float ra[8] = {a0.x, a0.y, a0.z, a0.w, a1.x, a1.y, a1.z, a1.w};
            float rb[8] = {b0.x, b0.y, b0.z, b0.w, b1.x, b1.y, b1.z, b1.w};
#pragma unroll
            for (int i = 0; i < 8; i++)
#pragma unroll
                for (int j = 0; j < 8; j++) acc[i][j] += ra[i] * rb[j];
        }
        __syncthreads();
    }

    // Epilogue: scatter into [B,H,S,DK]
#pragma unroll
    for (int i = 0; i < 8; i++) {
        int m = bm * 128 + ty * 8 + i;
        int b = m >> 11;            // /S_
        int s = m & 2047;
#pragma unroll
        for (int j = 0; j < 8; j++) {
            int n = bn * 128 + tx * 8 + j;
            int h = n >> 6;         // /DK_
            int d = n & 63;
            float v = acc[i][j] + bias[n];
            if (SCALE) v *= 0.125f;  // 1/sqrt(64)
            out[(((size_t)(b * H_ + h) * S_) + s) * DK_ + d] = v;
        }
    }
}

// ---------------------------------------------------------------------------
// Flash attention (fp32): one block per (64-row q-tile, batch*head).
// Q pre-scaled by 1/sqrt(DK). Online softmax over 32 K/V tiles of 64 rows.
// 256 threads. smem: Qs/Ks/Vs/Ss [64][68] + m/l/alpha rows.
// ---------------------------------------------------------------------------
#define PAD 68

__global__ __launch_bounds__(256, 2)
void attn_kernel(const int* __restrict__ mask, float* __restrict__ out)
{
    extern __shared__ float sm[];
    float* Qs   = sm;                  // 64*68
    float* Ks   = Qs + 64 * PAD;
    float* Vs   = Ks + 64 * PAD;
    float* Ss   = Vs + 64 * PAD;
    float* mrow = Ss + 64 * PAD;       // 64
    float* lrow = mrow + 64;           // 64
    float* arow = lrow + 64;           // 64

    const int tid  = threadIdx.x;
    const int qblk = blockIdx.x;       // 0..31
    const int bh   = blockIdx.y;       // 0..63
    const int b    = bh >> 4;
    const int h    = bh & 15;

    const float* Qg = g_Q + (size_t)bh * S_ * DK_ + (size_t)qblk * 64 * DK_;
    const float* Kg = g_K + (size_t)bh * S_ * DK_;
    const float* Vg = g_V + (size_t)bh * S_ * DK_;

    // Load Q tile (64x64), 4 float4 per thread
#pragma unroll
    for (int p = 0; p < 4; p++) {
        int idx = p * 256 + tid;       // 1024 float4s total
        int r = idx >> 4;
        int c = (idx & 15) * 4;
        *(float4*)(&Qs[r * PAD + c]) = *(const float4*)(Qg + r * 64 + c);
    }
    if (tid < 64) { mrow[tid] = -1e30f; lrow[tid] = 0.f; arow[tid] = 0.f; }

    // QK mapping: rows rq*2 .. +1, cols cq*8 .. +7
    const int rq = tid >> 3;
    const int cq = tid & 7;
    // PV mapping: row rp, dk cols dp..dp+15
    const int rp = tid >> 2;
    const int dp = (tid & 3) * 16;

    float O[16];
#pragma unroll
    for (int i = 0; i < 16; i++) O[i] = 0.f;

    __syncthreads();

    for (int t = 0; t < 32; t++) {
        // Load K,V tiles (64x64 each)
#pragma unroll
        for (int p = 0; p < 4; p++) {
            int idx = p * 256 + tid;
            int r = idx >> 4;
            int c = (idx & 15) * 4;
            *(float4*)(&Ks[r * PAD + c]) = *(const float4*)(Kg + (size_t)(t * 64 + r) * 64 + c);
            *(float4*)(&Vs[r * PAD + c]) = *(const float4*)(Vg + (size_t)(t * 64 + r) * 64 + c);
        }
        __syncthreads();

        // ---- scores s[2][8] = Q K^T (Q pre-scaled) ----
        float s0[8], s1[8];
#pragma unroll
        for (int j = 0; j < 8; j++) { s0[j] = 0.f; s1[j] = 0.f; }
#pragma unroll
        for (int k4 = 0; k4 < 16; k4++) {
            float4 q0 = *(const float4*)(&Qs[(rq * 2 + 0) * PAD + k4 * 4]);
            float4 q1 = *(const float4*)(&Qs[(rq * 2 + 1) * PAD + k4 * 4]);
#pragma unroll
            for (int j = 0; j < 8; j++) {
                float4 kk = *(const float4*)(&Ks[(cq * 8 + j) * PAD + k4 * 4]);
                s0[j] += q0.x * kk.x + q0.y * kk.y + q0.z * kk.z + q0.w * kk.w;
                s1[j] += q1.x * kk.x + q1.y * kk.y + q1.z * kk.z + q1.w * kk.w;
            }
        }

        // ---- mask ----
        {
            int q0g = qblk * 64 + rq * 2;
            int kg0 = t * 64 + cq * 8;
            const int* mp = mask + ((size_t)b * S_ + q0g) * S_ + kg0;
#pragma unroll
            for (int j = 0; j < 8; j++) {
                if (mp[j] == 0)      s0[j] = -1e9f;
                if (mp[S_ + j] == 0) s1[j] = -1e9f;
            }
        }

        // ---- online softmax (rows rq*2, rq*2+1; reduce over 8 lanes) ----
        float mx0 = s0[0], mx1 = s1[0];
#pragma unroll
        for (int j = 1; j < 8; j++) { mx0 = fmaxf(mx0, s0[j]); mx1 = fmaxf(mx1, s1[j]); }
#pragma unroll
        for (int o = 1; o < 8; o <<= 1) {
            mx0 = fmaxf(mx0, __shfl_xor_sync(0xffffffffu, mx0, o));
            mx1 = fmaxf(mx1, __shfl_xor_sync(0xffffffffu, mx1, o));
        }
        float mo0 = mrow[rq * 2 + 0];
        float mo1 = mrow[rq * 2 + 1];
        float mn0 = fmaxf(mo0, mx0);
        float mn1 = fmaxf(mo1, mx1);

        float ls0 = 0.f, ls1 = 0.f;
#pragma unroll
        for (int j = 0; j < 8; j++) {
            s0[j] = __expf(s0[j] - mn0); ls0 += s0[j];
            s1[j] = __expf(s1[j] - mn1); ls1 += s1[j];
        }
#pragma unroll
        for (int o = 1; o < 8; o <<= 1) {
            ls0 += __shfl_xor_sync(0xffffffffu, ls0, o);
            ls1 += __shfl_xor_sync(0xffffffffu, ls1, o);
        }
        __syncwarp();
        if (cq == 0) {
            float a0 = __expf(mo0 - mn0);
            float a1 = __expf(mo1 - mn1);
            mrow[rq * 2 + 0] = mn0;
            mrow[rq * 2 + 1] = mn1;
            lrow[rq * 2 + 0] = lrow[rq * 2 + 0] * a0 + ls0;
            lrow[rq * 2 + 1] = lrow[rq * 2 + 1] * a1 + ls1;
            arow[rq * 2 + 0] = a0;
            arow[rq * 2 + 1] = a1;
        }
        // stage P
#pragma unroll
        for (int j = 0; j < 8; j++) {
            Ss[(rq * 2 + 0) * PAD + cq * 8 + j] = s0[j];
            Ss[(rq * 2 + 1) * PAD + cq * 8 + j] = s1[j];
        }
        __syncthreads();

        // ---- O = O*alpha + P V ----
        {
            float a = arow[rp];
#pragma unroll
            for (int i = 0; i < 16; i++) O[i] *= a;
#pragma unroll 8
            for (int j = 0; j < 64; j++) {
                float pj = Ss[rp * PAD + j];
                float4 v0 = *(const float4*)(&Vs[j * PAD + dp + 0]);
                float4 v1 = *(const float4*)(&Vs[j * PAD + dp + 4]);
                float4 v2 = *(const float4*)(&Vs[j * PAD + dp + 8]);
                float4 v3 = *(const float4*)(&Vs[j * PAD + dp + 12]);
                O[0]  += pj * v0.x; O[1]  += pj * v0.y; O[2]  += pj * v0.z; O[3]  += pj * v0.w;
                O[4]  += pj * v1.x; O[5]  += pj * v1.y; O[6]  += pj * v1.z; O[7]  += pj * v1.w;
                O[8]  += pj * v2.x; O[9]  += pj * v2.y; O[10] += pj * v2.z; O[11] += pj * v2.w;
                O[12] += pj * v3.x; O[13] += pj * v3.y; O[14] += pj * v3.z; O[15] += pj * v3.w;
            }
        }
        __syncthreads();
    }

    // ---- finalize: O / l, write [B,S,D] with D index = h*64 + d ----
    float inv = 1.f / lrow[rp];
    int qg = qblk * 64 + rp;
    float* op = out + ((size_t)b * S_ + qg) * D_ + h * 64 + dp;
    float4 o;
    o.x = O[0] * inv;  o.y = O[1] * inv;  o.z = O[2] * inv;  o.w = O[3] * inv;
    *(float4*)(op + 0) = o;
    o.x = O[4] * inv;  o.y = O[5] * inv;  o.z = O[6] * inv;  o.w = O[7] * inv;
    *(float4*)(op + 4) = o;
    o.x = O[8] * inv;  o.y = O[9] * inv;  o.z = O[10] * inv; o.w = O[11] * inv;
    *(float4*)(op + 8) = o;
    o.x = O[12] * inv; o.y = O[13] * inv; o.z = O[14] * inv; o.w = O[15] * inv;
    *(float4*)(op + 12) = o;
}

// ---------------------------------------------------------------------------
// Launch
// Inputs (metadata order): query, key, value, mask, Wq, bq, Wk, bk, Wv, bv
// ---------------------------------------------------------------------------
extern "C" void kernel_launch(void* const* d_in, const int* in_sizes, int n_in,
                              void* d_out, int out_size)
{
    const float* query = (const float*)d_in[0];
    const float* key   = (const float*)d_in[1];
    const float* value = (const float*)d_in[2];
    const int*   mask  = (const int*)  d_in[3];
    const float* Wq    = (const float*)d_in[4];
    const float* bq    = (const float*)d_in[5];
    const float* Wk    = (const float*)d_in[6];
    const float* bk    = (const float*)d_in[7];
    const float* Wv    = (const float*)d_in[8];
    const float* bv    = (const float*)d_in[9];
    float* out = (float*)d_out;

    float *qptr, *kptr, *vptr;
    cudaGetSymbolAddress((void**)&qptr, g_Q);
    cudaGetSymbolAddress((void**)&kptr, g_K);
    cudaGetSymbolAddress((void**)&vptr, g_V);

    dim3 pgrid(8, 64);   // N/128, M/128
    proj_kernel<true ><<<pgrid, 256>>>(query, Wq, bq, qptr);
    proj_kernel<false><<<pgrid, 256>>>(key,   Wk, bk, kptr);
    proj_kernel<false><<<pgrid, 256>>>(value, Wv, bv, vptr);

    const int smem = (4 * 64 * PAD + 3 * 64) * (int)sizeof(float);
    cudaFuncSetAttribute(attn_kernel, cudaFuncAttributeMaxDynamicSharedMemorySize, smem);
    dim3 agrid(32, 64);  // q-tiles, B*H
    attn_kernel<<<agrid, 256, smem>>>(mask, out);
}

// round 3
// speedup vs baseline: 5.8532x; 5.8532x over previous
#include <cuda_runtime.h>
#include <cstdint>
#include <math.h>

// Problem constants
#define B_  4
#define S_  2048
#define D_  1024
#define H_  16
#define DK_ 64

// Scratch: projected Q,K,V in [B,H,S,DK] layout (device globals — no allocs)
__device__ float g_Q[(size_t)B_ * H_ * S_ * DK_];
__device__ float g_K[(size_t)B_ * H_ * S_ * DK_];
__device__ float g_V[(size_t)B_ * H_ * S_ * DK_];

// ---------------------------------------------------------------------------
// Projection GEMM: out = X @ W^T + bias, scattered into [B,H,S,DK].
// Q pre-scaled by 1/sqrt(DK).
// ---------------------------------------------------------------------------
template <bool SCALE>
__global__ __launch_bounds__(256, 2)
void proj_kernel(const float* __restrict__ X, const float* __restrict__ W,
                 const float* __restrict__ bias, float* __restrict__ out)
{
    __shared__ float As[8][128];
    __shared__ float Bs[8][128];

    const int tid = threadIdx.x;
    const int bm = blockIdx.y;
    const int bn = blockIdx.x;
    const int tx = tid & 15;
    const int ty = tid >> 4;
    const int lr = tid >> 1;
    const int lc = (tid & 1) * 4;

    const float* Aptr = X + (size_t)(bm * 128 + lr) * 1024 + lc;
    const float* Bptr = W + (size_t)(bn * 128 + lr) * 1024 + lc;

    float acc[8][8];
#pragma unroll
    for (int i = 0; i < 8; i++)
#pragma unroll
        for (int j = 0; j < 8; j++) acc[i][j] = 0.f;

    for (int k0 = 0; k0 < 1024; k0 += 8) {
        float4 a = *(const float4*)(Aptr + k0);
        float4 b = *(const float4*)(Bptr + k0);
        As[lc + 0][lr] = a.x; As[lc + 1][lr] = a.y;
        As[lc + 2][lr] = a.z; As[lc + 3][lr] = a.w;
        Bs[lc + 0][lr] = b.x; Bs[lc + 1][lr] = b.y;
        Bs[lc + 2][lr] = b.z; Bs[lc + 3][lr] = b.w;
        __syncthreads();

#pragma unroll
        for (int k = 0; k < 8; k++) {
            float4 a0 = *(const float4*)&As[k][ty * 8];
            float4 a1 = *(const float4*)&As[k][ty * 8 + 4];
            float4 b0 = *(const float4*)&Bs[k][tx * 8];
            float4 b1 = *(const float4*)&Bs[k][tx * 8 + 4];
            float ra[8] = {a0.x, a0.y, a0.z, a0.w, a1.x, a1.y, a1.z, a1.w};
            float rb[8] = {b0.x, b0.y, b0.z, b0.w, b1.x, b1.y, b1.z, b1.w};
#pragma unroll
            for (int i = 0; i < 8; i++)
#pragma unroll
                for (int j = 0; j < 8; j++) acc[i][j] += ra[i] * rb[j];
        }
        __syncthreads();
    }

#pragma unroll
    for (int i = 0; i < 8; i++) {
        int m = bm * 128 + ty * 8 + i;
        int b = m >> 11;
        int s = m & 2047;
#pragma unroll
        for (int j = 0; j < 8; j++) {
            int n = bn * 128 + tx * 8 + j;
            int h = n >> 6;
            int d = n & 63;
            float v = acc[i][j] + bias[n];
            if (SCALE) v *= 0.125f;
            out[(((size_t)(b * H_ + h) * S_) + s) * DK_ + d] = v;
        }
    }
}

// ---------------------------------------------------------------------------
// TF32 mma helpers
// ---------------------------------------------------------------------------
__device__ __forceinline__ uint32_t f2tf(float x) {
    uint32_t r;
    asm("cvt.rna.tf32.f32 %0, %1;" : "=r"(r) : "f"(x));
    return r;
}

__device__ __forceinline__ void mma_tf32(float& d0, float& d1, float& d2, float& d3,
                                         uint32_t a0, uint32_t a1, uint32_t a2, uint32_t a3,
                                         uint32_t b0, uint32_t b1)
{
    asm volatile(
        "mma.sync.aligned.m16n8k8.row.col.f32.tf32.tf32.f32 "
        "{%0,%1,%2,%3},{%4,%5,%6,%7},{%8,%9},{%0,%1,%2,%3};"
        : "+f"(d0), "+f"(d1), "+f"(d2), "+f"(d3)
        : "r"(a0), "r"(a1), "r"(a2), "r"(a3), "r"(b0), "r"(b1));
}

// ---------------------------------------------------------------------------
// Flash attention, TF32 tensor-core version.
// CTA: 128 q-rows x one (b,h). 8 warps, each owns 16 q-rows.
// Iterates over 32 tiles of 64 keys with online softmax.
// Q fragments register-resident; O accumulators register-resident.
// smem: Ks (64x68 tf32), Vs (64x72 tf32), Ss/P (128x68 tf32), bias (128x68 f32)
// ---------------------------------------------------------------------------
#define KS_STRIDE 68
#define VS_STRIDE 72
#define SS_STRIDE 68

__global__ __launch_bounds__(256, 2)
void attn_mma(const int* __restrict__ mask, float* __restrict__ out)
{
    extern __shared__ uint32_t smu[];
    uint32_t* Ks = smu;                          // 64*68  = 4352
    uint32_t* Vs = Ks + 64 * KS_STRIDE;          // 64*72  = 4608
    uint32_t* Ss = Vs + 64 * VS_STRIDE;          // 128*68 = 8704
    float*    Bi = (float*)(Ss + 128 * SS_STRIDE); // 128*68 = 8704

    const int tid  = threadIdx.x;
    const int warp = tid >> 5;
    const int lane = tid & 31;
    const int grp  = lane >> 2;   // 0..7
    const int lid4 = lane & 3;    // 0..3

    const int qblk = blockIdx.x;  // 0..15 (128-row q tiles)
    const int bh   = blockIdx.y;  // 0..63
    const int b    = bh >> 4;
    const int h    = bh & 15;

    const float* Qg = g_Q + (size_t)bh * S_ * DK_ + (size_t)qblk * 128 * DK_;
    const float* Kg = g_K + (size_t)bh * S_ * DK_;
    const float* Vg = g_V + (size_t)bh * S_ * DK_;

    const int row0 = warp * 16 + grp;   // q row within tile
    const int row1 = row0 + 8;

    // ---- stage Q tile (128x64) into Ss (as float): 2048 float4s, 8 passes ----
    {
        float* Qs = (float*)Ss;
#pragma unroll
        for (int p = 0; p < 8; p++) {
            int idx = p * 256 + tid;
            int r = idx >> 4;            // 0..127
            int c = (idx & 15) * 4;      // 0..60
            *(float4*)&Qs[r * SS_STRIDE + c] = *(const float4*)(Qg + r * 64 + c);
        }
    }
    __syncthreads();

    uint32_t qa[8][4];   // A fragments: 8 k-chunks of 8
    {
        const float* Qs = (const float*)Ss;
#pragma unroll
        for (int kc = 0; kc < 8; kc++) {
            int c = kc * 8 + lid4;
            qa[kc][0] = f2tf(Qs[row0 * SS_STRIDE + c]);
            qa[kc][1] = f2tf(Qs[row1 * SS_STRIDE + c]);
            qa[kc][2] = f2tf(Qs[row0 * SS_STRIDE + c + 4]);
            qa[kc][3] = f2tf(Qs[row1 * SS_STRIDE + c + 4]);
        }
    }

    float o[8][4];
#pragma unroll
    for (int nf = 0; nf < 8; nf++)
#pragma unroll
        for (int i = 0; i < 4; i++) o[nf][i] = 0.f;

    float m0 = -1e30f, m1 = -1e30f, l0 = 0.f, l1 = 0.f;

    const int* maskg = mask + (size_t)b * S_ * S_ + (size_t)(qblk * 128) * S_;

    for (int t = 0; t < 32; t++) {
        __syncthreads();   // previous tile fully consumed

        // ---- load K, V (fp32 -> tf32), mask -> additive bias ----
#pragma unroll
        for (int p = 0; p < 4; p++) {
            int idx = p * 256 + tid;
            int r = idx >> 4;
            int c = (idx & 15) * 4;
            float4 kv = *(const float4*)(Kg + (size_t)(t * 64 + r) * 64 + c);
            float4 vv = *(const float4*)(Vg + (size_t)(t * 64 + r) * 64 + c);
            *(uint4*)&Ks[r * KS_STRIDE + c] =
                make_uint4(f2tf(kv.x), f2tf(kv.y), f2tf(kv.z), f2tf(kv.w));
            *(uint4*)&Vs[r * VS_STRIDE + c] =
                make_uint4(f2tf(vv.x), f2tf(vv.y), f2tf(vv.z), f2tf(vv.w));
        }
#pragma unroll
        for (int p = 0; p < 8; p++) {
            int idx = p * 256 + tid;
            int r = idx >> 4;            // q row 0..127
            int c = (idx & 15) * 4;      // key col
            int4 mv = *(const int4*)(maskg + (size_t)r * S_ + t * 64 + c);
            float4 bv;
            bv.x = mv.x ? 0.f : -1e9f;
            bv.y = mv.y ? 0.f : -1e9f;
            bv.z = mv.z ? 0.f : -1e9f;
            bv.w = mv.w ? 0.f : -1e9f;
            *(float4*)&Bi[r * SS_STRIDE + c] = bv;
        }
        __syncthreads();

        // ---- scores: S = Q K^T (Q pre-scaled by 1/8) ----
        float sc[8][4];
#pragma unroll
        for (int nf = 0; nf < 8; nf++) {
            sc[nf][0] = 0.f; sc[nf][1] = 0.f; sc[nf][2] = 0.f; sc[nf][3] = 0.f;
#pragma unroll
            for (int kc = 0; kc < 8; kc++) {
                int kb = kc * 8 + lid4;
                uint32_t b0 = Ks[(nf * 8 + grp) * KS_STRIDE + kb];
                uint32_t b1 = Ks[(nf * 8 + grp) * KS_STRIDE + kb + 4];
                mma_tf32(sc[nf][0], sc[nf][1], sc[nf][2], sc[nf][3],
                         qa[kc][0], qa[kc][1], qa[kc][2], qa[kc][3], b0, b1);
            }
        }

        // ---- add mask bias, online softmax ----
        float tm0 = -1e30f, tm1 = -1e30f;
#pragma unroll
        for (int nf = 0; nf < 8; nf++) {
            int cb = nf * 8 + 2 * lid4;
            float2 b0 = *(const float2*)&Bi[row0 * SS_STRIDE + cb];
            float2 b1 = *(const float2*)&Bi[row1 * SS_STRIDE + cb];
            sc[nf][0] += b0.x; sc[nf][1] += b0.y;
            sc[nf][2] += b1.x; sc[nf][3] += b1.y;
            tm0 = fmaxf(tm0, fmaxf(sc[nf][0], sc[nf][1]));
            tm1 = fmaxf(tm1, fmaxf(sc[nf][2], sc[nf][3]));
        }
        tm0 = fmaxf(tm0, __shfl_xor_sync(0xffffffffu, tm0, 1));
        tm0 = fmaxf(tm0, __shfl_xor_sync(0xffffffffu, tm0, 2));
        tm1 = fmaxf(tm1, __shfl_xor_sync(0xffffffffu, tm1, 1));
        tm1 = fmaxf(tm1, __shfl_xor_sync(0xffffffffu, tm1, 2));

        float mn0 = fmaxf(m0, tm0);
        float mn1 = fmaxf(m1, tm1);
        float al0 = __expf(m0 - mn0);
        float al1 = __expf(m1 - mn1);
        m0 = mn0; m1 = mn1;

        float rs0 = 0.f, rs1 = 0.f;
#pragma unroll
        for (int nf = 0; nf < 8; nf++) {
            float p00 = __expf(sc[nf][0] - mn0);
            float p01 = __expf(sc[nf][1] - mn0);
            float p10 = __expf(sc[nf][2] - mn1);
            float p11 = __expf(sc[nf][3] - mn1);
            rs0 += p00 + p01;
            rs1 += p10 + p11;
            int cb = nf * 8 + 2 * lid4;
            *(uint2*)&Ss[row0 * SS_STRIDE + cb] = make_uint2(f2tf(p00), f2tf(p01));
            *(uint2*)&Ss[row1 * SS_STRIDE + cb] = make_uint2(f2tf(p10), f2tf(p11));
            o[nf][0] *= al0; o[nf][1] *= al0;
            o[nf][2] *= al1; o[nf][3] *= al1;
        }
        rs0 += __shfl_xor_sync(0xffffffffu, rs0, 1);
        rs0 += __shfl_xor_sync(0xffffffffu, rs0, 2);
        rs1 += __shfl_xor_sync(0xffffffffu, rs1, 1);
        rs1 += __shfl_xor_sync(0xffffffffu, rs1, 2);
        l0 = l0 * al0 + rs0;
        l1 = l1 * al1 + rs1;

        __syncwarp();   // P round-trip is warp-local (each warp owns its 16 rows)

        // ---- O += P V ----
#pragma unroll
        for (int kc = 0; kc < 8; kc++) {
            int kb = kc * 8 + lid4;
            uint32_t a0 = Ss[row0 * SS_STRIDE + kb];
            uint32_t a1 = Ss[row1 * SS_STRIDE + kb];
            uint32_t a2 = Ss[row0 * SS_STRIDE + kb + 4];
            uint32_t a3 = Ss[row1 * SS_STRIDE + kb + 4];
#pragma unroll
            for (int nf = 0; nf < 8; nf++) {
                uint32_t b0 = Vs[kb * VS_STRIDE + nf * 8 + grp];
                uint32_t b1 = Vs[(kb + 4) * VS_STRIDE + nf * 8 + grp];
                mma_tf32(o[nf][0], o[nf][1], o[nf][2], o[nf][3],
                         a0, a1, a2, a3, b0, b1);
            }
        }
    }

    // ---- finalize: O / l, write to out[B,S,D] ----
    float inv0 = 1.f / l0;
    float inv1 = 1.f / l1;
    int qg0 = qblk * 128 + row0;
    int qg1 = qblk * 128 + row1;
    float* op0 = out + ((size_t)b * S_ + qg0) * D_ + h * 64;
    float* op1 = out + ((size_t)b * S_ + qg1) * D_ + h * 64;
#pragma unroll
    for (int nf = 0; nf < 8; nf++) {
        int cb = nf * 8 + 2 * lid4;
        *(float2*)(op0 + cb) = make_float2(o[nf][0] * inv0, o[nf][1] * inv0);
        *(float2*)(op1 + cb) = make_float2(o[nf][2] * inv1, o[nf][3] * inv1);
    }
}

// ---------------------------------------------------------------------------
// Launch
// Inputs (metadata order): query, key, value, mask, Wq, bq, Wk, bk, Wv, bv
// ---------------------------------------------------------------------------
extern "C" void kernel_launch(void* const* d_in, const int* in_sizes, int n_in,
                              void* d_out, int out_size)
{
    const float* query = (const float*)d_in[0];
    const float* key   = (const float*)d_in[1];
    const float* value = (const float*)d_in[2];
    const int*   mask  = (const int*)  d_in[3];
    const float* Wq    = (const float*)d_in[4];
    const float* bq    = (const float*)d_in[5];
    const float* Wk    = (const float*)d_in[6];
    const float* bk    = (const float*)d_in[7];
    const float* Wv    = (const float*)d_in[8];
    const float* bv    = (const float*)d_in[9];
    float* out = (float*)d_out;

    float *qptr, *kptr, *vptr;
    cudaGetSymbolAddress((void**)&qptr, g_Q);
    cudaGetSymbolAddress((void**)&kptr, g_K);
    cudaGetSymbolAddress((void**)&vptr, g_V);

    dim3 pgrid(8, 64);
    proj_kernel<true ><<<pgrid, 256>>>(query, Wq, bq, qptr);
    proj_kernel<false><<<pgrid, 256>>>(key,   Wk, bk, kptr);
    proj_kernel<false><<<pgrid, 256>>>(value, Wv, bv, vptr);

    const int smem_words = 64 * KS_STRIDE + 64 * VS_STRIDE
                         + 128 * SS_STRIDE + 128 * SS_STRIDE;
    const int smem = smem_words * (int)sizeof(uint32_t);
    cudaFuncSetAttribute(attn_mma, cudaFuncAttributeMaxDynamicSharedMemorySize, smem);

    dim3 agrid(16, 64);   // 128-row q tiles, B*H
    attn_mma<<<agrid, 256, smem>>>(mask, out);
}

// round 4
// speedup vs baseline: 10.8244x; 1.8493x over previous
#include <cuda_runtime.h>
#include <cstdint>
#include <math.h>

// Problem constants
#define B_  4
#define S_  2048
#define D_  1024
#define H_  16
#define DK_ 64

// Scratch: projected Q,K,V in [B,H,S,DK] layout (device globals — no allocs)
__device__ float g_Q[(size_t)B_ * H_ * S_ * DK_];
__device__ float g_K[(size_t)B_ * H_ * S_ * DK_];
__device__ float g_V[(size_t)B_ * H_ * S_ * DK_];

// ---------------------------------------------------------------------------
// bf16 helpers
// ---------------------------------------------------------------------------
// Split two fp32 into bf16x2 (hi) and bf16x2 (lo residual): x ~= hi + lo with
// ~2^-17 relative error. Packed k-major: element 0 in low 16 bits.
__device__ __forceinline__ void cvt_hilo(float x0, float x1, uint32_t& hi, uint32_t& lo)
{
    uint32_t h;
    asm("cvt.rn.bf16x2.f32 %0, %1, %2;" : "=r"(h) : "f"(x1), "f"(x0));
    float h0 = __uint_as_float(h << 16);
    float h1 = __uint_as_float(h & 0xffff0000u);
    float l0 = x0 - h0;
    float l1 = x1 - h1;
    uint32_t l;
    asm("cvt.rn.bf16x2.f32 %0, %1, %2;" : "=r"(l) : "f"(l1), "f"(l0));
    hi = h; lo = l;
}

__device__ __forceinline__ void mma_bf16(float* d, const uint32_t* a,
                                         uint32_t b0, uint32_t b1)
{
    asm volatile(
        "mma.sync.aligned.m16n8k16.row.col.f32.bf16.bf16.f32 "
        "{%0,%1,%2,%3},{%4,%5,%6,%7},{%8,%9},{%0,%1,%2,%3};"
        : "+f"(d[0]), "+f"(d[1]), "+f"(d[2]), "+f"(d[3])
        : "r"(a[0]), "r"(a[1]), "r"(a[2]), "r"(a[3]), "r"(b0), "r"(b1));
}

// ---------------------------------------------------------------------------
// Projection GEMM on tensor cores, bf16x3 (full fp32-equivalent precision).
// C[8192,1024] = X @ W^T + bias, scattered into [B,H,S,DK].
// CTA tile 128x128x32; 8 warps (2x4), warp tile 64x32.
// smem planes: bf16x2 pairs, row stride 20 words (16 k-pairs + 4 pad).
// ---------------------------------------------------------------------------
#define PSTRIDE 20

template <bool SCALE>
__global__ __launch_bounds__(256)
void proj_tc(const float* __restrict__ X, const float* __restrict__ W,
             const float* __restrict__ bias, float* __restrict__ out)
{
    __shared__ uint32_t sXhi[128 * PSTRIDE];
    __shared__ uint32_t sXlo[128 * PSTRIDE];
    __shared__ uint32_t sWhi[128 * PSTRIDE];
    __shared__ uint32_t sWlo[128 * PSTRIDE];

    const int tid  = threadIdx.x;
    const int warp = tid >> 5;
    const int lane = tid & 31;
    const int grp  = lane >> 2;     // 0..7
    const int t4   = lane & 3;      // 0..3
    const int bm   = blockIdx.y;    // 0..63
    const int bn   = blockIdx.x;    // 0..7
    const int wm   = (warp >> 2) * 64;   // warp row offset in tile
    const int wn   = (warp & 3) * 32;    // warp col offset in tile

    const int lr = tid >> 3;        // 0..31  (load row within 32-row group)
    const int lc = tid & 7;         // 0..7   (float4 column)

    const float* Xp = X + ((size_t)(bm * 128 + lr) << 10) + lc * 4;
    const float* Wp = W + ((size_t)(bn * 128 + lr) << 10) + lc * 4;

    // Prologue: load first k-tile into registers
    float4 xr[4], wr[4];
#pragma unroll
    for (int p = 0; p < 4; p++) {
        xr[p] = *(const float4*)(Xp + (size_t)p * 32 * 1024);
        wr[p] = *(const float4*)(Wp + (size_t)p * 32 * 1024);
    }

    float acc[4][4][4];
#pragma unroll
    for (int mf = 0; mf < 4; mf++)
#pragma unroll
        for (int nf = 0; nf < 4; nf++)
#pragma unroll
            for (int i = 0; i < 4; i++) acc[mf][nf][i] = 0.f;

    for (int ks = 0; ks < 32; ks++) {
        __syncthreads();   // previous tile fully consumed

        // Convert fp32 -> (hi,lo) bf16x2 pairs and store planes
#pragma unroll
        for (int p = 0; p < 4; p++) {
            int row = p * 32 + lr;
            int a = row * PSTRIDE + lc * 2;
            uint32_t h0, l0, h1, l1;
            cvt_hilo(xr[p].x, xr[p].y, h0, l0);
            cvt_hilo(xr[p].z, xr[p].w, h1, l1);
            *(uint2*)&sXhi[a] = make_uint2(h0, h1);
            *(uint2*)&sXlo[a] = make_uint2(l0, l1);
            cvt_hilo(wr[p].x, wr[p].y, h0, l0);
            cvt_hilo(wr[p].z, wr[p].w, h1, l1);
            *(uint2*)&sWhi[a] = make_uint2(h0, h1);
            *(uint2*)&sWlo[a] = make_uint2(l0, l1);
        }
        __syncthreads();

        // Issue next k-tile loads (overlap with MMA below)
        if (ks < 31) {
            int k0 = (ks + 1) * 32;
#pragma unroll
            for (int p = 0; p < 4; p++) {
                xr[p] = *(const float4*)(Xp + (size_t)p * 32 * 1024 + k0);
                wr[p] = *(const float4*)(Wp + (size_t)p * 32 * 1024 + k0);
            }
        }

        // Compute: 2 k16 chunks
#pragma unroll
        for (int kc = 0; kc < 2; kc++) {
            const int kp = kc * 8 + t4;
            uint32_t ah[4][4], al[4][4];
#pragma unroll
            for (int mf = 0; mf < 4; mf++) {
                int r0 = wm + mf * 16 + grp;
                ah[mf][0] = sXhi[r0 * PSTRIDE + kp];
                ah[mf][1] = sXhi[(r0 + 8) * PSTRIDE + kp];
                ah[mf][2] = sXhi[r0 * PSTRIDE + kp + 4];
                ah[mf][3] = sXhi[(r0 + 8) * PSTRIDE + kp + 4];
                al[mf][0] = sXlo[r0 * PSTRIDE + kp];
                al[mf][1] = sXlo[(r0 + 8) * PSTRIDE + kp];
                al[mf][2] = sXlo[r0 * PSTRIDE + kp + 4];
                al[mf][3] = sXlo[(r0 + 8) * PSTRIDE + kp + 4];
            }
#pragma unroll
            for (int nf = 0; nf < 4; nf++) {
                int n = wn + nf * 8 + grp;
                uint32_t bh0 = sWhi[n * PSTRIDE + kp];
                uint32_t bh1 = sWhi[n * PSTRIDE + kp + 4];
                uint32_t bl0 = sWlo[n * PSTRIDE + kp];
                uint32_t bl1 = sWlo[n * PSTRIDE + kp + 4];
#pragma unroll
                for (int mf = 0; mf < 4; mf++) {
                    mma_bf16(acc[mf][nf], ah[mf], bh0, bh1);   // hi*hi
                    mma_bf16(acc[mf][nf], ah[mf], bl0, bl1);   // hi*lo
                    mma_bf16(acc[mf][nf], al[mf], bh0, bh1);   // lo*hi
                }
            }
        }
    }

    // Epilogue: add bias, optional scale, scatter into [B,H,S,DK]
#pragma unroll
    for (int mf = 0; mf < 4; mf++) {
        int row0 = bm * 128 + wm + mf * 16 + grp;
        int row1 = row0 + 8;
        int b0i = row0 >> 11, s0 = row0 & 2047;
        int b1i = row1 >> 11, s1 = row1 & 2047;
#pragma unroll
        for (int nf = 0; nf < 4; nf++) {
            int col = bn * 128 + wn + nf * 8 + 2 * t4;
            int h = col >> 6;
            int d = col & 63;
            float bb0 = bias[col], bb1 = bias[col + 1];
            float v00 = acc[mf][nf][0] + bb0;
            float v01 = acc[mf][nf][1] + bb1;
            float v10 = acc[mf][nf][2] + bb0;
            float v11 = acc[mf][nf][3] + bb1;
            if (SCALE) { v00 *= 0.125f; v01 *= 0.125f; v10 *= 0.125f; v11 *= 0.125f; }
            *(float2*)&out[(((size_t)(b0i * H_ + h) * S_) + s0) * DK_ + d] = make_float2(v00, v01);
            *(float2*)&out[(((size_t)(b1i * H_ + h) * S_) + s1) * DK_ + d] = make_float2(v10, v11);
        }
    }
}

// ---------------------------------------------------------------------------
// TF32 mma helpers (attention)
// ---------------------------------------------------------------------------
__device__ __forceinline__ uint32_t f2tf(float x) {
    uint32_t r;
    asm("cvt.rna.tf32.f32 %0, %1;" : "=r"(r) : "f"(x));
    return r;
}

__device__ __forceinline__ void mma_tf32(float& d0, float& d1, float& d2, float& d3,
                                         uint32_t a0, uint32_t a1, uint32_t a2, uint32_t a3,
                                         uint32_t b0, uint32_t b1)
{
    asm volatile(
        "mma.sync.aligned.m16n8k8.row.col.f32.tf32.tf32.f32 "
        "{%0,%1,%2,%3},{%4,%5,%6,%7},{%8,%9},{%0,%1,%2,%3};"
        : "+f"(d0), "+f"(d1), "+f"(d2), "+f"(d3)
        : "r"(a0), "r"(a1), "r"(a2), "r"(a3), "r"(b0), "r"(b1));
}

// ---------------------------------------------------------------------------
// Flash attention, TF32 tensor-core version (unchanged from round 3).
// ---------------------------------------------------------------------------
#define KS_STRIDE 68
#define VS_STRIDE 72
#define SS_STRIDE 68

__global__ __launch_bounds__(256, 2)
void attn_mma(const int* __restrict__ mask, float* __restrict__ out)
{
    extern __shared__ uint32_t smu[];
    uint32_t* Ks = smu;
    uint32_t* Vs = Ks + 64 * KS_STRIDE;
    uint32_t* Ss = Vs + 64 * VS_STRIDE;
    float*    Bi = (float*)(Ss + 128 * SS_STRIDE);

    const int tid  = threadIdx.x;
    const int warp = tid >> 5;
    const int lane = tid & 31;
    const int grp  = lane >> 2;
    const int lid4 = lane & 3;

    const int qblk = blockIdx.x;
    const int bh   = blockIdx.y;
    const int b    = bh >> 4;
    const int h    = bh & 15;

    const float* Qg = g_Q + (size_t)bh * S_ * DK_ + (size_t)qblk * 128 * DK_;
    const float* Kg = g_K + (size_t)bh * S_ * DK_;
    const float* Vg = g_V + (size_t)bh * S_ * DK_;

    const int row0 = warp * 16 + grp;
    const int row1 = row0 + 8;

    // stage Q tile (128x64): 2048 float4s, 8 passes
    {
        float* Qs = (float*)Ss;
#pragma unroll
        for (int p = 0; p < 8; p++) {
            int idx = p * 256 + tid;
            int r = idx >> 4;
            int c = (idx & 15) * 4;
            *(float4*)&Qs[r * SS_STRIDE + c] = *(const float4*)(Qg + r * 64 + c);
        }
    }
    __syncthreads();

    uint32_t qa[8][4];
    {
        const float* Qs = (const float*)Ss;
#pragma unroll
        for (int kc = 0; kc < 8; kc++) {
            int c = kc * 8 + lid4;
            qa[kc][0] = f2tf(Qs[row0 * SS_STRIDE + c]);
            qa[kc][1] = f2tf(Qs[row1 * SS_STRIDE + c]);
            qa[kc][2] = f2tf(Qs[row0 * SS_STRIDE + c + 4]);
            qa[kc][3] = f2tf(Qs[row1 * SS_STRIDE + c + 4]);
        }
    }

    float o[8][4];
#pragma unroll
    for (int nf = 0; nf < 8; nf++)
#pragma unroll
        for (int i = 0; i < 4; i++) o[nf][i] = 0.f;

    float m0 = -1e30f, m1 = -1e30f, l0 = 0.f, l1 = 0.f;

    const int* maskg = mask + (size_t)b * S_ * S_ + (size_t)(qblk * 128) * S_;

    for (int t = 0; t < 32; t++) {
        __syncthreads();

#pragma unroll
        for (int p = 0; p < 4; p++) {
            int idx = p * 256 + tid;
            int r = idx >> 4;
            int c = (idx & 15) * 4;
            float4 kv = *(const float4*)(Kg + (size_t)(t * 64 + r) * 64 + c);
            float4 vv = *(const float4*)(Vg + (size_t)(t * 64 + r) * 64 + c);
            *(uint4*)&Ks[r * KS_STRIDE + c] =
                make_uint4(f2tf(kv.x), f2tf(kv.y), f2tf(kv.z), f2tf(kv.w));
            *(uint4*)&Vs[r * VS_STRIDE + c] =
                make_uint4(f2tf(vv.x), f2tf(vv.y), f2tf(vv.z), f2tf(vv.w));
        }
#pragma unroll
        for (int p = 0; p < 8; p++) {
            int idx = p * 256 + tid;
            int r = idx >> 4;
            int c = (idx & 15) * 4;
            int4 mv = *(const int4*)(maskg + (size_t)r * S_ + t * 64 + c);
            float4 bv;
            bv.x = mv.x ? 0.f : -1e9f;
            bv.y = mv.y ? 0.f : -1e9f;
            bv.z = mv.z ? 0.f : -1e9f;
            bv.w = mv.w ? 0.f : -1e9f;
            *(float4*)&Bi[r * SS_STRIDE + c] = bv;
        }
        __syncthreads();

        float sc[8][4];
#pragma unroll
        for (int nf = 0; nf < 8; nf++) {
            sc[nf][0] = 0.f; sc[nf][1] = 0.f; sc[nf][2] = 0.f; sc[nf][3] = 0.f;
#pragma unroll
            for (int kc = 0; kc < 8; kc++) {
                int kb = kc * 8 + lid4;
                uint32_t b0 = Ks[(nf * 8 + grp) * KS_STRIDE + kb];
                uint32_t b1 = Ks[(nf * 8 + grp) * KS_STRIDE + kb + 4];
                mma_tf32(sc[nf][0], sc[nf][1], sc[nf][2], sc[nf][3],
                         qa[kc][0], qa[kc][1], qa[kc][2], qa[kc][3], b0, b1);
            }
        }

        float tm0 = -1e30f, tm1 = -1e30f;
#pragma unroll
        for (int nf = 0; nf < 8; nf++) {
            int cb = nf * 8 + 2 * lid4;
            float2 b0 = *(const float2*)&Bi[row0 * SS_STRIDE + cb];
            float2 b1 = *(const float2*)&Bi[row1 * SS_STRIDE + cb];
            sc[nf][0] += b0.x; sc[nf][1] += b0.y;
            sc[nf][2] += b1.x; sc[nf][3] += b1.y;
            tm0 = fmaxf(tm0, fmaxf(sc[nf][0], sc[nf][1]));
            tm1 = fmaxf(tm1, fmaxf(sc[nf][2], sc[nf][3]));
        }
        tm0 = fmaxf(tm0, __shfl_xor_sync(0xffffffffu, tm0, 1));
        tm0 = fmaxf(tm0, __shfl_xor_sync(0xffffffffu, tm0, 2));
        tm1 = fmaxf(tm1, __shfl_xor_sync(0xffffffffu, tm1, 1));
        tm1 = fmaxf(tm1, __shfl_xor_sync(0xffffffffu, tm1, 2));

        float mn0 = fmaxf(m0, tm0);
        float mn1 = fmaxf(m1, tm1);
        float al0 = __expf(m0 - mn0);
        float al1 = __expf(m1 - mn1);
        m0 = mn0; m1 = mn1;

        float rs0 = 0.f, rs1 = 0.f;
#pragma unroll
        for (int nf = 0; nf < 8; nf++) {
            float p00 = __expf(sc[nf][0] - mn0);
            float p01 = __expf(sc[nf][1] - mn0);
            float p10 = __expf(sc[nf][2] - mn1);
            float p11 = __expf(sc[nf][3] - mn1);
            rs0 += p00 + p01;
            rs1 += p10 + p11;
            int cb = nf * 8 + 2 * lid4;
            *(uint2*)&Ss[row0 * SS_STRIDE + cb] = make_uint2(f2tf(p00), f2tf(p01));
            *(uint2*)&Ss[row1 * SS_STRIDE + cb] = make_uint2(f2tf(p10), f2tf(p11));
            o[nf][0] *= al0; o[nf][1] *= al0;
            o[nf][2] *= al1; o[nf][3] *= al1;
        }
        rs0 += __shfl_xor_sync(0xffffffffu, rs0, 1);
        rs0 += __shfl_xor_sync(0xffffffffu, rs0, 2);
        rs1 += __shfl_xor_sync(0xffffffffu, rs1, 1);
        rs1 += __shfl_xor_sync(0xffffffffu, rs1, 2);
        l0 = l0 * al0 + rs0;
        l1 = l1 * al1 + rs1;

        __syncwarp();

#pragma unroll
        for (int kc = 0; kc < 8; kc++) {
            int kb = kc * 8 + lid4;
            uint32_t a0 = Ss[row0 * SS_STRIDE + kb];
            uint32_t a1 = Ss[row1 * SS_STRIDE + kb];
            uint32_t a2 = Ss[row0 * SS_STRIDE + kb + 4];
            uint32_t a3 = Ss[row1 * SS_STRIDE + kb + 4];
#pragma unroll
            for (int nf = 0; nf < 8; nf++) {
                uint32_t b0 = Vs[kb * VS_STRIDE + nf * 8 + grp];
                uint32_t b1 = Vs[(kb + 4) * VS_STRIDE + nf * 8 + grp];
                mma_tf32(o[nf][0], o[nf][1], o[nf][2], o[nf][3],
                         a0, a1, a2, a3, b0, b1);
            }
        }
    }

    float inv0 = 1.f / l0;
    float inv1 = 1.f / l1;
    int qg0 = qblk * 128 + row0;
    int qg1 = qblk * 128 + row1;
    float* op0 = out + ((size_t)b * S_ + qg0) * D_ + h * 64;
    float* op1 = out + ((size_t)b * S_ + qg1) * D_ + h * 64;
#pragma unroll
    for (int nf = 0; nf < 8; nf++) {
        int cb = nf * 8 + 2 * lid4;
        *(float2*)(op0 + cb) = make_float2(o[nf][0] * inv0, o[nf][1] * inv0);
        *(float2*)(op1 + cb) = make_float2(o[nf][2] * inv1, o[nf][3] * inv1);
    }
}

// ---------------------------------------------------------------------------
// Launch
// Inputs (metadata order): query, key, value, mask, Wq, bq, Wk, bk, Wv, bv
// ---------------------------------------------------------------------------
extern "C" void kernel_launch(void* const* d_in, const int* in_sizes, int n_in,
                              void* d_out, int out_size)
{
    const float* query = (const float*)d_in[0];
    const float* key   = (const float*)d_in[1];
    const float* value = (const float*)d_in[2];
    const int*   mask  = (const int*)  d_in[3];
    const float* Wq    = (const float*)d_in[4];
    const float* bq    = (const float*)d_in[5];
    const float* Wk    = (const float*)d_in[6];
    const float* bk    = (const float*)d_in[7];
    const float* Wv    = (const float*)d_in[8];
    const float* bv    = (const float*)d_in[9];
    float* out = (float*)d_out;

    float *qptr, *kptr, *vptr;
    cudaGetSymbolAddress((void**)&qptr, g_Q);
    cudaGetSymbolAddress((void**)&kptr, g_K);
    cudaGetSymbolAddress((void**)&vptr, g_V);

    dim3 pgrid(8, 64);   // N/128, M/128
    proj_tc<true ><<<pgrid, 256>>>(query, Wq, bq, qptr);
    proj_tc<false><<<pgrid, 256>>>(key,   Wk, bk, kptr);
    proj_tc<false><<<pgrid, 256>>>(value, Wv, bv, vptr);

    const int smem_words = 64 * KS_STRIDE + 64 * VS_STRIDE
                         + 128 * SS_STRIDE + 128 * SS_STRIDE;
    const int smem = smem_words * (int)sizeof(uint32_t);
    cudaFuncSetAttribute(attn_mma, cudaFuncAttributeMaxDynamicSharedMemorySize, smem);

    dim3 agrid(16, 64);   // 128-row q tiles, B*H
    attn_mma<<<agrid, 256, smem>>>(mask, out);
}

// round 5
// speedup vs baseline: 10.8276x; 1.0003x over previous
#include <cuda_runtime.h>
#include <cstdint>
#include <math.h>

// Problem constants
#define B_  4
#define S_  2048
#define D_  1024
#define H_  16
#define DK_ 64

// Scratch: projected Q,K,V in [B,H,S,DK] layout (device globals — no allocs)
__device__ float g_Q[(size_t)B_ * H_ * S_ * DK_];
__device__ float g_K[(size_t)B_ * H_ * S_ * DK_];
__device__ float g_V[(size_t)B_ * H_ * S_ * DK_];

// ---------------------------------------------------------------------------
// bf16 helpers (projection)
// ---------------------------------------------------------------------------
__device__ __forceinline__ void cvt_hilo(float x0, float x1, uint32_t& hi, uint32_t& lo)
{
    uint32_t h;
    asm("cvt.rn.bf16x2.f32 %0, %1, %2;" : "=r"(h) : "f"(x1), "f"(x0));
    float h0 = __uint_as_float(h << 16);
    float h1 = __uint_as_float(h & 0xffff0000u);
    float l0 = x0 - h0;
    float l1 = x1 - h1;
    uint32_t l;
    asm("cvt.rn.bf16x2.f32 %0, %1, %2;" : "=r"(l) : "f"(l1), "f"(l0));
    hi = h; lo = l;
}

__device__ __forceinline__ void mma_bf16(float* d, const uint32_t* a,
                                         uint32_t b0, uint32_t b1)
{
    asm volatile(
        "mma.sync.aligned.m16n8k16.row.col.f32.bf16.bf16.f32 "
        "{%0,%1,%2,%3},{%4,%5,%6,%7},{%8,%9},{%0,%1,%2,%3};"
        : "+f"(d[0]), "+f"(d[1]), "+f"(d[2]), "+f"(d[3])
        : "r"(a[0]), "r"(a[1]), "r"(a[2]), "r"(a[3]), "r"(b0), "r"(b1));
}

// ---------------------------------------------------------------------------
// Projection GEMM on tensor cores, bf16x3 (unchanged from round 4).
// ---------------------------------------------------------------------------
#define PSTRIDE 20

template <bool SCALE>
__global__ __launch_bounds__(256)
void proj_tc(const float* __restrict__ X, const float* __restrict__ W,
             const float* __restrict__ bias, float* __restrict__ out)
{
    __shared__ uint32_t sXhi[128 * PSTRIDE];
    __shared__ uint32_t sXlo[128 * PSTRIDE];
    __shared__ uint32_t sWhi[128 * PSTRIDE];
    __shared__ uint32_t sWlo[128 * PSTRIDE];

    const int tid  = threadIdx.x;
    const int warp = tid >> 5;
    const int lane = tid & 31;
    const int grp  = lane >> 2;
    const int t4   = lane & 3;
    const int bm   = blockIdx.y;
    const int bn   = blockIdx.x;
    const int wm   = (warp >> 2) * 64;
    const int wn   = (warp & 3) * 32;

    const int lr = tid >> 3;
    const int lc = tid & 7;

    const float* Xp = X + ((size_t)(bm * 128 + lr) << 10) + lc * 4;
    const float* Wp = W + ((size_t)(bn * 128 + lr) << 10) + lc * 4;

    float4 xr[4], wr[4];
#pragma unroll
    for (int p = 0; p < 4; p++) {
        xr[p] = *(const float4*)(Xp + (size_t)p * 32 * 1024);
        wr[p] = *(const float4*)(Wp + (size_t)p * 32 * 1024);
    }

    float acc[4][4][4];
#pragma unroll
    for (int mf = 0; mf < 4; mf++)
#pragma unroll
        for (int nf = 0; nf < 4; nf++)
#pragma unroll
            for (int i = 0; i < 4; i++) acc[mf][nf][i] = 0.f;

    for (int ks = 0; ks < 32; ks++) {
        __syncthreads();

#pragma unroll
        for (int p = 0; p < 4; p++) {
            int row = p * 32 + lr;
            int a = row * PSTRIDE + lc * 2;
            uint32_t h0, l0, h1, l1;
            cvt_hilo(xr[p].x, xr[p].y, h0, l0);
            cvt_hilo(xr[p].z, xr[p].w, h1, l1);
            *(uint2*)&sXhi[a] = make_uint2(h0, h1);
            *(uint2*)&sXlo[a] = make_uint2(l0, l1);
            cvt_hilo(wr[p].x, wr[p].y, h0, l0);
            cvt_hilo(wr[p].z, wr[p].w, h1, l1);
            *(uint2*)&sWhi[a] = make_uint2(h0, h1);
            *(uint2*)&sWlo[a] = make_uint2(l0, l1);
        }
        __syncthreads();

        if (ks < 31) {
            int k0 = (ks + 1) * 32;
#pragma unroll
            for (int p = 0; p < 4; p++) {
                xr[p] = *(const float4*)(Xp + (size_t)p * 32 * 1024 + k0);
                wr[p] = *(const float4*)(Wp + (size_t)p * 32 * 1024 + k0);
            }
        }

#pragma unroll
        for (int kc = 0; kc < 2; kc++) {
            const int kp = kc * 8 + t4;
            uint32_t ah[4][4], al[4][4];
#pragma unroll
            for (int mf = 0; mf < 4; mf++) {
                int r0 = wm + mf * 16 + grp;
                ah[mf][0] = sXhi[r0 * PSTRIDE + kp];
                ah[mf][1] = sXhi[(r0 + 8) * PSTRIDE + kp];
                ah[mf][2] = sXhi[r0 * PSTRIDE + kp + 4];
                ah[mf][3] = sXhi[(r0 + 8) * PSTRIDE + kp + 4];
                al[mf][0] = sXlo[r0 * PSTRIDE + kp];
                al[mf][1] = sXlo[(r0 + 8) * PSTRIDE + kp];
                al[mf][2] = sXlo[r0 * PSTRIDE + kp + 4];
                al[mf][3] = sXlo[(r0 + 8) * PSTRIDE + kp + 4];
            }
#pragma unroll
            for (int nf = 0; nf < 4; nf++) {
                int n = wn + nf * 8 + grp;
                uint32_t bh0 = sWhi[n * PSTRIDE + kp];
                uint32_t bh1 = sWhi[n * PSTRIDE + kp + 4];
                uint32_t bl0 = sWlo[n * PSTRIDE + kp];
                uint32_t bl1 = sWlo[n * PSTRIDE + kp + 4];
#pragma unroll
                for (int mf = 0; mf < 4; mf++) {
                    mma_bf16(acc[mf][nf], ah[mf], bh0, bh1);
                    mma_bf16(acc[mf][nf], ah[mf], bl0, bl1);
                    mma_bf16(acc[mf][nf], al[mf], bh0, bh1);
                }
            }
        }
    }

#pragma unroll
    for (int mf = 0; mf < 4; mf++) {
        int row0 = bm * 128 + wm + mf * 16 + grp;
        int row1 = row0 + 8;
        int b0i = row0 >> 11, s0 = row0 & 2047;
        int b1i = row1 >> 11, s1 = row1 & 2047;
#pragma unroll
        for (int nf = 0; nf < 4; nf++) {
            int col = bn * 128 + wn + nf * 8 + 2 * t4;
            int h = col >> 6;
            int d = col & 63;
            float bb0 = bias[col], bb1 = bias[col + 1];
            float v00 = acc[mf][nf][0] + bb0;
            float v01 = acc[mf][nf][1] + bb1;
            float v10 = acc[mf][nf][2] + bb0;
            float v11 = acc[mf][nf][3] + bb1;
            if (SCALE) { v00 *= 0.125f; v01 *= 0.125f; v10 *= 0.125f; v11 *= 0.125f; }
            *(float2*)&out[(((size_t)(b0i * H_ + h) * S_) + s0) * DK_ + d] = make_float2(v00, v01);
            *(float2*)&out[(((size_t)(b1i * H_ + h) * S_) + s1) * DK_ + d] = make_float2(v10, v11);
        }
    }
}

// ---------------------------------------------------------------------------
// TF32 mma helpers (attention)
// ---------------------------------------------------------------------------
__device__ __forceinline__ uint32_t f2tf(float x) {
    uint32_t r;
    asm("cvt.rna.tf32.f32 %0, %1;" : "=r"(r) : "f"(x));
    return r;
}

__device__ __forceinline__ void mma_tf32(float* d, const uint32_t* a,
                                         uint32_t b0, uint32_t b1)
{
    asm volatile(
        "mma.sync.aligned.m16n8k8.row.col.f32.tf32.tf32.f32 "
        "{%0,%1,%2,%3},{%4,%5,%6,%7},{%8,%9},{%0,%1,%2,%3};"
        : "+f"(d[0]), "+f"(d[1]), "+f"(d[2]), "+f"(d[3])
        : "r"(a[0]), "r"(a[1]), "r"(a[2]), "r"(a[3]), "r"(b0), "r"(b1));
}

__device__ __forceinline__ void cp_async16(uint32_t dst_smem, const void* src) {
    asm volatile("cp.async.cg.shared.global [%0], [%1], 16;"
                 :: "r"(dst_smem), "l"(src));
}

// ---------------------------------------------------------------------------
// Flash attention, TF32, mf=2 warp tiling.
// CTA: 256 threads (8 warps), 256-row q-tile; each warp owns 32 q-rows
// (rows w*32+grp+{0,8,16,24}); K/V B-fragments shared across the 2 m-frags.
// Mask via cp.async into int smem. Next K/V tile prefetched in registers.
// smem: Ks 64x68 tf32 | Vs 64x72 tf32 | Ss 256x68 (Q stage, then P) | Mi 256x68 int
// ---------------------------------------------------------------------------
#define AKS 68
#define AVS 72
#define ASS 68
#define AMS 68

__global__ __launch_bounds__(256, 1)
void attn_mma(const int* __restrict__ mask, float* __restrict__ out)
{
    extern __shared__ uint32_t smu[];
    uint32_t* Ks = smu;                        // 64*68
    uint32_t* Vs = Ks + 64 * AKS;              // 64*72
    uint32_t* Ss = Vs + 64 * AVS;              // 256*68
    int*      Mi = (int*)(Ss + 256 * ASS);     // 256*68 ints

    const int tid  = threadIdx.x;
    const int warp = tid >> 5;     // 0..7
    const int lane = tid & 31;
    const int grp  = lane >> 2;    // 0..7
    const int t4   = lane & 3;     // 0..3

    const int qblk = blockIdx.x;   // 0..7  (256-row q tiles)
    const int bh   = blockIdx.y;   // 0..63
    const int b    = bh >> 4;
    const int h    = bh & 15;

    const float* Qg = g_Q + (size_t)bh * S_ * DK_ + (size_t)qblk * 256 * DK_;
    const float* Kg = g_K + (size_t)bh * S_ * DK_;
    const float* Vg = g_V + (size_t)bh * S_ * DK_;
    const int* maskg = mask + (size_t)b * S_ * S_ + (size_t)(qblk * 256) * S_;

    const int r0 = warp * 32 + grp;   // mf rows: r0+mf*16, r0+mf*16+8

    // ---- stage Q tile (256x64) into Ss as float ----
    {
        float* Qs = (float*)Ss;
#pragma unroll
        for (int p = 0; p < 16; p++) {
            int idx = p * 256 + tid;
            int r = idx >> 4;            // 0..255
            int c = (idx & 15) * 4;
            *(float4*)&Qs[r * ASS + c] = *(const float4*)(Qg + (size_t)r * 64 + c);
        }
    }
    __syncthreads();

    // ---- extract register-resident Q fragments (tf32) ----
    uint32_t qa[2][8][4];
    {
        const float* Qs = (const float*)Ss;
#pragma unroll
        for (int mf = 0; mf < 2; mf++) {
            int ra = r0 + mf * 16, rb = ra + 8;
#pragma unroll
            for (int kc = 0; kc < 8; kc++) {
                int c = kc * 8 + t4;
                qa[mf][kc][0] = f2tf(Qs[ra * ASS + c]);
                qa[mf][kc][1] = f2tf(Qs[rb * ASS + c]);
                qa[mf][kc][2] = f2tf(Qs[ra * ASS + c + 4]);
                qa[mf][kc][3] = f2tf(Qs[rb * ASS + c + 4]);
            }
        }
    }
    __syncthreads();

    float o[2][8][4];
#pragma unroll
    for (int mf = 0; mf < 2; mf++)
#pragma unroll
        for (int nf = 0; nf < 8; nf++)
#pragma unroll
            for (int i = 0; i < 4; i++) o[mf][nf][i] = 0.f;

    float mrow[4] = {-1e30f, -1e30f, -1e30f, -1e30f};
    float lrow[4] = {0.f, 0.f, 0.f, 0.f};

    // ---- prologue: load K/V tile 0 into registers ----
    float4 kr[4], vr[4];
#pragma unroll
    for (int p = 0; p < 4; p++) {
        int idx = p * 256 + tid;
        int r = idx >> 4, c = (idx & 15) * 4;
        kr[p] = *(const float4*)(Kg + (size_t)r * 64 + c);
        vr[p] = *(const float4*)(Vg + (size_t)r * 64 + c);
    }

    for (int t = 0; t < 32; t++) {
        if (t) __syncthreads();    // prev tile's smem fully consumed

        // ---- stage K/V (tf32) from prefetch regs ----
#pragma unroll
        for (int p = 0; p < 4; p++) {
            int idx = p * 256 + tid;
            int r = idx >> 4, c = (idx & 15) * 4;
            *(uint4*)&Ks[r * AKS + c] =
                make_uint4(f2tf(kr[p].x), f2tf(kr[p].y), f2tf(kr[p].z), f2tf(kr[p].w));
            *(uint4*)&Vs[r * AVS + c] =
                make_uint4(f2tf(vr[p].x), f2tf(vr[p].y), f2tf(vr[p].z), f2tf(vr[p].w));
        }
        // ---- cp.async mask tile t (raw ints) ----
#pragma unroll
        for (int p = 0; p < 16; p++) {
            int idx = p * 256 + tid;
            int r = idx >> 4;           // 0..255
            int c4 = (idx & 15) * 4;    // int column (x4)
            uint32_t dst = (uint32_t)__cvta_generic_to_shared(&Mi[r * AMS + c4]);
            cp_async16(dst, maskg + (size_t)r * S_ + t * 64 + c4);
        }
        asm volatile("cp.async.commit_group;");
        __syncthreads();

        // ---- QK: both m-fragments share K B-fragments ----
        float sc[2][8][4];
#pragma unroll
        for (int nf = 0; nf < 8; nf++) {
#pragma unroll
            for (int i = 0; i < 4; i++) { sc[0][nf][i] = 0.f; sc[1][nf][i] = 0.f; }
#pragma unroll
            for (int kc = 0; kc < 8; kc++) {
                int kb = kc * 8 + t4;
                uint32_t b0 = Ks[(nf * 8 + grp) * AKS + kb];
                uint32_t b1 = Ks[(nf * 8 + grp) * AKS + kb + 4];
                mma_tf32(sc[0][nf], qa[0][kc], b0, b1);
                mma_tf32(sc[1][nf], qa[1][kc], b0, b1);
            }
        }

        asm volatile("cp.async.wait_group 0;");
        __syncthreads();   // mask visible to all threads

        // ---- prefetch next K/V tile (consumed at next loop top) ----
        if (t < 31) {
#pragma unroll
            for (int p = 0; p < 4; p++) {
                int idx = p * 256 + tid;
                int r = idx >> 4, c = (idx & 15) * 4;
                kr[p] = *(const float4*)(Kg + (size_t)((t + 1) * 64 + r) * 64 + c);
                vr[p] = *(const float4*)(Vg + (size_t)((t + 1) * 64 + r) * 64 + c);
            }
        }

        // ---- mask + online softmax per m-fragment ----
#pragma unroll
        for (int mf = 0; mf < 2; mf++) {
            int ra = r0 + mf * 16, rb = ra + 8;
            float tma = -1e30f, tmb = -1e30f;
#pragma unroll
            for (int nf = 0; nf < 8; nf++) {
                int2 ma = *(const int2*)&Mi[ra * AMS + nf * 8 + 2 * t4];
                int2 mb = *(const int2*)&Mi[rb * AMS + nf * 8 + 2 * t4];
                if (ma.x == 0) sc[mf][nf][0] = -1e9f;
                if (ma.y == 0) sc[mf][nf][1] = -1e9f;
                if (mb.x == 0) sc[mf][nf][2] = -1e9f;
                if (mb.y == 0) sc[mf][nf][3] = -1e9f;
                tma = fmaxf(tma, fmaxf(sc[mf][nf][0], sc[mf][nf][1]));
                tmb = fmaxf(tmb, fmaxf(sc[mf][nf][2], sc[mf][nf][3]));
            }
            tma = fmaxf(tma, __shfl_xor_sync(0xffffffffu, tma, 1));
            tma = fmaxf(tma, __shfl_xor_sync(0xffffffffu, tma, 2));
            tmb = fmaxf(tmb, __shfl_xor_sync(0xffffffffu, tmb, 1));
            tmb = fmaxf(tmb, __shfl_xor_sync(0xffffffffu, tmb, 2));

            float mna = fmaxf(mrow[2 * mf], tma);
            float mnb = fmaxf(mrow[2 * mf + 1], tmb);
            float ala = __expf(mrow[2 * mf] - mna);
            float alb = __expf(mrow[2 * mf + 1] - mnb);
            mrow[2 * mf] = mna; mrow[2 * mf + 1] = mnb;

            float rsa = 0.f, rsb = 0.f;
#pragma unroll
            for (int nf = 0; nf < 8; nf++) {
                float p00 = __expf(sc[mf][nf][0] - mna);
                float p01 = __expf(sc[mf][nf][1] - mna);
                float p10 = __expf(sc[mf][nf][2] - mnb);
                float p11 = __expf(sc[mf][nf][3] - mnb);
                rsa += p00 + p01;
                rsb += p10 + p11;
                int cb = nf * 8 + 2 * t4;
                *(uint2*)&Ss[ra * ASS + cb] = make_uint2(f2tf(p00), f2tf(p01));
                *(uint2*)&Ss[rb * ASS + cb] = make_uint2(f2tf(p10), f2tf(p11));
                o[mf][nf][0] *= ala; o[mf][nf][1] *= ala;
                o[mf][nf][2] *= alb; o[mf][nf][3] *= alb;
            }
            rsa += __shfl_xor_sync(0xffffffffu, rsa, 1);
            rsa += __shfl_xor_sync(0xffffffffu, rsa, 2);
            rsb += __shfl_xor_sync(0xffffffffu, rsb, 1);
            rsb += __shfl_xor_sync(0xffffffffu, rsb, 2);
            lrow[2 * mf]     = lrow[2 * mf] * ala + rsa;
            lrow[2 * mf + 1] = lrow[2 * mf + 1] * alb + rsb;
        }
        __syncwarp();   // P round-trip is warp-local

        // ---- PV: V B-fragments shared across the 2 m-fragments ----
#pragma unroll
        for (int kc = 0; kc < 8; kc++) {
            int kb = kc * 8 + t4;
            uint32_t pa[2][4];
#pragma unroll
            for (int mf = 0; mf < 2; mf++) {
                int ra = r0 + mf * 16, rb = ra + 8;
                pa[mf][0] = Ss[ra * ASS + kb];
                pa[mf][1] = Ss[rb * ASS + kb];
                pa[mf][2] = Ss[ra * ASS + kb + 4];
                pa[mf][3] = Ss[rb * ASS + kb + 4];
            }
#pragma unroll
            for (int nf = 0; nf < 8; nf++) {
                uint32_t b0 = Vs[kb * AVS + nf * 8 + grp];
                uint32_t b1 = Vs[(kb + 4) * AVS + nf * 8 + grp];
                mma_tf32(o[0][nf], pa[0], b0, b1);
                mma_tf32(o[1][nf], pa[1], b0, b1);
            }
        }
    }

    // ---- finalize: O / l, write [B,S,D] ----
#pragma unroll
    for (int mf = 0; mf < 2; mf++) {
        float inva = 1.f / lrow[2 * mf];
        float invb = 1.f / lrow[2 * mf + 1];
        int ga = qblk * 256 + r0 + mf * 16;
        int gb = ga + 8;
        float* opa = out + ((size_t)b * S_ + ga) * D_ + h * 64;
        float* opb = out + ((size_t)b * S_ + gb) * D_ + h * 64;
#pragma unroll
        for (int nf = 0; nf < 8; nf++) {
            int cb = nf * 8 + 2 * t4;
            *(float2*)(opa + cb) = make_float2(o[mf][nf][0] * inva, o[mf][nf][1] * inva);
            *(float2*)(opb + cb) = make_float2(o[mf][nf][2] * invb, o[mf][nf][3] * invb);
        }
    }
}

// ---------------------------------------------------------------------------
// Launch
// Inputs (metadata order): query, key, value, mask, Wq, bq, Wk, bk, Wv, bv
// ---------------------------------------------------------------------------
extern "C" void kernel_launch(void* const* d_in, const int* in_sizes, int n_in,
                              void* d_out, int out_size)
{
    const float* query = (const float*)d_in[0];
    const float* key   = (const float*)d_in[1];
    const float* value = (const float*)d_in[2];
    const int*   mask  = (const int*)  d_in[3];
    const float* Wq    = (const float*)d_in[4];
    const float* bq    = (const float*)d_in[5];
    const float* Wk    = (const float*)d_in[6];
    const float* bk    = (const float*)d_in[7];
    const float* Wv    = (const float*)d_in[8];
    const float* bv    = (const float*)d_in[9];
    float* out = (float*)d_out;

    float *qptr, *kptr, *vptr;
    cudaGetSymbolAddress((void**)&qptr, g_Q);
    cudaGetSymbolAddress((void**)&kptr, g_K);
    cudaGetSymbolAddress((void**)&vptr, g_V);

    dim3 pgrid(8, 64);
    proj_tc<true ><<<pgrid, 256>>>(query, Wq, bq, qptr);
    proj_tc<false><<<pgrid, 256>>>(key,   Wk, bk, kptr);
    proj_tc<false><<<pgrid, 256>>>(value, Wv, bv, vptr);

    const int smem_words = 64 * AKS + 64 * AVS + 256 * ASS + 256 * AMS;
    const int smem = smem_words * (int)sizeof(uint32_t);   // 175,104 B
    cudaFuncSetAttribute(attn_mma, cudaFuncAttributeMaxDynamicSharedMemorySize, smem);

    dim3 agrid(8, 64);   // 256-row q tiles, B*H
    attn_mma<<<agrid, 256, smem>>>(mask, out);
}

// round 6
// speedup vs baseline: 14.8266x; 1.3693x over previous
#include <cuda_runtime.h>
#include <cuda_fp16.h>
#include <cstdint>
#include <math.h>

// Problem constants
#define B_  4
#define S_  2048
#define D_  1024
#define H_  16
#define DK_ 64

// Scratch: projected Q,K,V in [B,H,S,DK] layout (device globals — no allocs)
__device__ float g_Q[(size_t)B_ * H_ * S_ * DK_];
__device__ float g_K[(size_t)B_ * H_ * S_ * DK_];
__device__ float g_V[(size_t)B_ * H_ * S_ * DK_];
// mask all-ones flags per (b, q256-tile, k64-tile)
__device__ int g_mflag[B_ * 8 * 32];

// ---------------------------------------------------------------------------
// bf16 helpers (projection)
// ---------------------------------------------------------------------------
__device__ __forceinline__ void cvt_hilo(float x0, float x1, uint32_t& hi, uint32_t& lo)
{
    uint32_t h;
    asm("cvt.rn.bf16x2.f32 %0, %1, %2;" : "=r"(h) : "f"(x1), "f"(x0));
    float h0 = __uint_as_float(h << 16);
    float h1 = __uint_as_float(h & 0xffff0000u);
    float l0 = x0 - h0;
    float l1 = x1 - h1;
    uint32_t l;
    asm("cvt.rn.bf16x2.f32 %0, %1, %2;" : "=r"(l) : "f"(l1), "f"(l0));
    hi = h; lo = l;
}

__device__ __forceinline__ void mma_bf16(float* d, const uint32_t* a,
                                         uint32_t b0, uint32_t b1)
{
    asm volatile(
        "mma.sync.aligned.m16n8k16.row.col.f32.bf16.bf16.f32 "
        "{%0,%1,%2,%3},{%4,%5,%6,%7},{%8,%9},{%0,%1,%2,%3};"
        : "+f"(d[0]), "+f"(d[1]), "+f"(d[2]), "+f"(d[3])
        : "r"(a[0]), "r"(a[1]), "r"(a[2]), "r"(a[3]), "r"(b0), "r"(b1));
}

// ---------------------------------------------------------------------------
// Projection GEMM on tensor cores, bf16x3 (unchanged — proven).
// ---------------------------------------------------------------------------
#define PSTRIDE 20

template <bool SCALE>
__global__ __launch_bounds__(256)
void proj_tc(const float* __restrict__ X, const float* __restrict__ W,
             const float* __restrict__ bias, float* __restrict__ out)
{
    __shared__ uint32_t sXhi[128 * PSTRIDE];
    __shared__ uint32_t sXlo[128 * PSTRIDE];
    __shared__ uint32_t sWhi[128 * PSTRIDE];
    __shared__ uint32_t sWlo[128 * PSTRIDE];

    const int tid  = threadIdx.x;
    const int warp = tid >> 5;
    const int lane = tid & 31;
    const int grp  = lane >> 2;
    const int t4   = lane & 3;
    const int bm   = blockIdx.y;
    const int bn   = blockIdx.x;
    const int wm   = (warp >> 2) * 64;
    const int wn   = (warp & 3) * 32;

    const int lr = tid >> 3;
    const int lc = tid & 7;

    const float* Xp = X + ((size_t)(bm * 128 + lr) << 10) + lc * 4;
    const float* Wp = W + ((size_t)(bn * 128 + lr) << 10) + lc * 4;

    float4 xr[4], wr[4];
#pragma unroll
    for (int p = 0; p < 4; p++) {
        xr[p] = *(const float4*)(Xp + (size_t)p * 32 * 1024);
        wr[p] = *(const float4*)(Wp + (size_t)p * 32 * 1024);
    }

    float acc[4][4][4];
#pragma unroll
    for (int mf = 0; mf < 4; mf++)
#pragma unroll
        for (int nf = 0; nf < 4; nf++)
#pragma unroll
            for (int i = 0; i < 4; i++) acc[mf][nf][i] = 0.f;

    for (int ks = 0; ks < 32; ks++) {
        __syncthreads();

#pragma unroll
        for (int p = 0; p < 4; p++) {
            int row = p * 32 + lr;
            int a = row * PSTRIDE + lc * 2;
            uint32_t h0, l0, h1, l1;
            cvt_hilo(xr[p].x, xr[p].y, h0, l0);
            cvt_hilo(xr[p].z, xr[p].w, h1, l1);
            *(uint2*)&sXhi[a] = make_uint2(h0, h1);
            *(uint2*)&sXlo[a] = make_uint2(l0, l1);
            cvt_hilo(wr[p].x, wr[p].y, h0, l0);
            cvt_hilo(wr[p].z, wr[p].w, h1, l1);
            *(uint2*)&sWhi[a] = make_uint2(h0, h1);
            *(uint2*)&sWlo[a] = make_uint2(l0, l1);
        }
        __syncthreads();

        if (ks < 31) {
            int k0 = (ks + 1) * 32;
#pragma unroll
            for (int p = 0; p < 4; p++) {
                xr[p] = *(const float4*)(Xp + (size_t)p * 32 * 1024 + k0);
                wr[p] = *(const float4*)(Wp + (size_t)p * 32 * 1024 + k0);
            }
        }

#pragma unroll
        for (int kc = 0; kc < 2; kc++) {
            const int kp = kc * 8 + t4;
            uint32_t ah[4][4], al[4][4];
#pragma unroll
            for (int mf = 0; mf < 4; mf++) {
                int r0 = wm + mf * 16 + grp;
                ah[mf][0] = sXhi[r0 * PSTRIDE + kp];
                ah[mf][1] = sXhi[(r0 + 8) * PSTRIDE + kp];
                ah[mf][2] = sXhi[r0 * PSTRIDE + kp + 4];
                ah[mf][3] = sXhi[(r0 + 8) * PSTRIDE + kp + 4];
                al[mf][0] = sXlo[r0 * PSTRIDE + kp];
                al[mf][1] = sXlo[(r0 + 8) * PSTRIDE + kp];
                al[mf][2] = sXlo[r0 * PSTRIDE + kp + 4];
                al[mf][3] = sXlo[(r0 + 8) * PSTRIDE + kp + 4];
            }
#pragma unroll
            for (int nf = 0; nf < 4; nf++) {
                int n = wn + nf * 8 + grp;
                uint32_t bh0 = sWhi[n * PSTRIDE + kp];
                uint32_t bh1 = sWhi[n * PSTRIDE + kp + 4];
                uint32_t bl0 = sWlo[n * PSTRIDE + kp];
                uint32_t bl1 = sWlo[n * PSTRIDE + kp + 4];
#pragma unroll
                for (int mf = 0; mf < 4; mf++) {
                    mma_bf16(acc[mf][nf], ah[mf], bh0, bh1);
                    mma_bf16(acc[mf][nf], ah[mf], bl0, bl1);
                    mma_bf16(acc[mf][nf], al[mf], bh0, bh1);
                }
            }
        }
    }

#pragma unroll
    for (int mf = 0; mf < 4; mf++) {
        int row0 = bm * 128 + wm + mf * 16 + grp;
        int row1 = row0 + 8;
        int b0i = row0 >> 11, s0 = row0 & 2047;
        int b1i = row1 >> 11, s1 = row1 & 2047;
#pragma unroll
        for (int nf = 0; nf < 4; nf++) {
            int col = bn * 128 + wn + nf * 8 + 2 * t4;
            int h = col >> 6;
            int d = col & 63;
            float bb0 = bias[col], bb1 = bias[col + 1];
            float v00 = acc[mf][nf][0] + bb0;
            float v01 = acc[mf][nf][1] + bb1;
            float v10 = acc[mf][nf][2] + bb0;
            float v11 = acc[mf][nf][3] + bb1;
            if (SCALE) { v00 *= 0.125f; v01 *= 0.125f; v10 *= 0.125f; v11 *= 0.125f; }
            *(float2*)&out[(((size_t)(b0i * H_ + h) * S_) + s0) * DK_ + d] = make_float2(v00, v01);
            *(float2*)&out[(((size_t)(b1i * H_ + h) * S_) + s1) * DK_ + d] = make_float2(v10, v11);
        }
    }
}

// ---------------------------------------------------------------------------
// Mask scan: flag[b][qt][kt] = 1 iff mask[b, qt*256:+256, kt*64:+64] all nonzero
// ---------------------------------------------------------------------------
__global__ void mask_scan(const int* __restrict__ mask)
{
    const int kt = blockIdx.x;   // 0..31
    const int qt = blockIdx.y;   // 0..7
    const int b  = blockIdx.z;   // 0..3
    const int* rp = mask + ((size_t)b * S_ + qt * 256 + threadIdx.x) * S_ + kt * 64;
    int ok = 1;
#pragma unroll
    for (int c = 0; c < 64; c += 4) {
        int4 v = *(const int4*)(rp + c);
        ok &= (v.x != 0) & (v.y != 0) & (v.z != 0) & (v.w != 0);
    }
    ok = __syncthreads_and(ok);
    if (threadIdx.x == 0) g_mflag[(b * 8 + qt) * 32 + kt] = ok;
}

// ---------------------------------------------------------------------------
// FP16 mma helper (attention): m16n8k16, fp32 accum
// ---------------------------------------------------------------------------
__device__ __forceinline__ void mma_fp16(float* d, const uint32_t* a,
                                         uint32_t b0, uint32_t b1)
{
    asm volatile(
        "mma.sync.aligned.m16n8k16.row.col.f32.f16.f16.f32 "
        "{%0,%1,%2,%3},{%4,%5,%6,%7},{%8,%9},{%0,%1,%2,%3};"
        : "+f"(d[0]), "+f"(d[1]), "+f"(d[2]), "+f"(d[3])
        : "r"(a[0]), "r"(a[1]), "r"(a[2]), "r"(a[3]), "r"(b0), "r"(b1));
}

__device__ __forceinline__ uint32_t f16pk(float x0, float x1) {
    __half2 h = __floats2half2_rn(x0, x1);   // .x (low) = x0
    return *(uint32_t*)&h;
}

__device__ __forceinline__ void cp_async16(uint32_t dst_smem, const void* src) {
    asm volatile("cp.async.cg.shared.global [%0], [%1], 16;"
                 :: "r"(dst_smem), "l"(src));
}

// ---------------------------------------------------------------------------
// Flash attention, FP16 m16n8k16, mf=2 warp tiling, mask elision.
// CTA: 256 threads (8 warps), 256-row q-tile; warp owns 32 q-rows.
// smem (uint32 words):
//   Kpk 64x36 (fp16x2 pairs along k) | Vpk 32x72 (pairs across key rows)
//   Ppk 256x36 (P pairs along key)   | Mi 256x68 ints (mask; doubles as Q stage)
// ---------------------------------------------------------------------------
#define KPS 36
#define VPS 72
#define PPS 36
#define AMS 68

__global__ __launch_bounds__(256, 1)
void attn_mma(const int* __restrict__ mask, float* __restrict__ out)
{
    extern __shared__ uint32_t smu[];
    uint32_t* Kpk = smu;                         // 64*36  = 2304
    uint32_t* Vpk = Kpk + 64 * KPS;              // 32*72  = 2304
    uint32_t* Ppk = Vpk + 32 * VPS;              // 256*36 = 9216
    int*      Mi  = (int*)(Ppk + 256 * PPS);     // 256*68 = 17408

    const int tid  = threadIdx.x;
    const int warp = tid >> 5;     // 0..7
    const int lane = tid & 31;
    const int grp  = lane >> 2;    // 0..7
    const int t4   = lane & 3;     // 0..3

    const int qblk = blockIdx.x;   // 0..7
    const int bh   = blockIdx.y;   // 0..63
    const int b    = bh >> 4;
    const int h    = bh & 15;

    const float* Qg = g_Q + (size_t)bh * S_ * DK_ + (size_t)qblk * 256 * DK_;
    const float* Kg = g_K + (size_t)bh * S_ * DK_;
    const float* Vg = g_V + (size_t)bh * S_ * DK_;
    const int* maskg = mask + (size_t)b * S_ * S_ + (size_t)(qblk * 256) * S_;
    const int* mfl = g_mflag + (b * 8 + qblk) * 32;

    const int r0 = warp * 32 + grp;   // mf rows: r0+mf*16, +8

    // ---- stage Q tile (256x64 fp32) into Mi region ----
    {
        float* Qs = (float*)Mi;
#pragma unroll
        for (int p = 0; p < 16; p++) {
            int idx = p * 256 + tid;
            int r = idx >> 4;
            int c = (idx & 15) * 4;
            *(float4*)&Qs[r * AMS + c] = *(const float4*)(Qg + (size_t)r * 64 + c);
        }
    }
    __syncthreads();

    // ---- extract register-resident Q fragments (packed fp16x2) ----
    uint32_t qa[2][4][4];
    {
        const float* Qs = (const float*)Mi;
#pragma unroll
        for (int mf = 0; mf < 2; mf++) {
            int ra = r0 + mf * 16, rb = ra + 8;
#pragma unroll
            for (int kc = 0; kc < 4; kc++) {
                int c = kc * 16 + 2 * t4;
                qa[mf][kc][0] = f16pk(Qs[ra * AMS + c],     Qs[ra * AMS + c + 1]);
                qa[mf][kc][1] = f16pk(Qs[rb * AMS + c],     Qs[rb * AMS + c + 1]);
                qa[mf][kc][2] = f16pk(Qs[ra * AMS + c + 8], Qs[ra * AMS + c + 9]);
                qa[mf][kc][3] = f16pk(Qs[rb * AMS + c + 8], Qs[rb * AMS + c + 9]);
            }
        }
    }
    __syncthreads();   // Q stage fully consumed before Mi reused for mask

    float o[2][8][4];
#pragma unroll
    for (int mf = 0; mf < 2; mf++)
#pragma unroll
        for (int nf = 0; nf < 8; nf++)
#pragma unroll
            for (int i = 0; i < 4; i++) o[mf][nf][i] = 0.f;

    float mrow[4] = {-1e30f, -1e30f, -1e30f, -1e30f};
    float lrow[4] = {0.f, 0.f, 0.f, 0.f};

    // K prefetch mapping: r = idx>>4 (row), c = (idx&15)*4
    // V prefetch mapping: row-pairs: pr = p*16 + (tid>>4), rows 2pr / 2pr+1
    const int kr_r = tid >> 4;          // base row (per pass: +16p)
    const int kr_c = (tid & 15) * 4;

    float4 kr[4], vra[2], vrb[2];
#pragma unroll
    for (int p = 0; p < 4; p++)
        kr[p] = *(const float4*)(Kg + (size_t)(p * 16 + kr_r) * 64 + kr_c);
#pragma unroll
    for (int p = 0; p < 2; p++) {
        int pr = p * 16 + kr_r;
        vra[p] = *(const float4*)(Vg + (size_t)(2 * pr) * 64 + kr_c);
        vrb[p] = *(const float4*)(Vg + (size_t)(2 * pr + 1) * 64 + kr_c);
    }

    for (int t = 0; t < 32; t++) {
        const int allones = mfl[t];
        if (t) __syncthreads();    // prev tile's smem fully consumed

        // ---- stage K (pairs along k) and V (pairs across rows) as fp16x2 ----
#pragma unroll
        for (int p = 0; p < 4; p++) {
            int r = p * 16 + kr_r;
            *(uint2*)&Kpk[r * KPS + (kr_c >> 1)] =
                make_uint2(f16pk(kr[p].x, kr[p].y), f16pk(kr[p].z, kr[p].w));
        }
#pragma unroll
        for (int p = 0; p < 2; p++) {
            int pr = p * 16 + kr_r;
            *(uint4*)&Vpk[pr * VPS + kr_c] =
                make_uint4(f16pk(vra[p].x, vrb[p].x), f16pk(vra[p].y, vrb[p].y),
                           f16pk(vra[p].z, vrb[p].z), f16pk(vra[p].w, vrb[p].w));
        }
        if (!allones) {
#pragma unroll
            for (int p = 0; p < 16; p++) {
                int idx = p * 256 + tid;
                int r = idx >> 4;
                int c4 = (idx & 15) * 4;
                uint32_t dst = (uint32_t)__cvta_generic_to_shared(&Mi[r * AMS + c4]);
                cp_async16(dst, maskg + (size_t)r * S_ + t * 64 + c4);
            }
            asm volatile("cp.async.commit_group;");
        }
        __syncthreads();

        // ---- QK: fp16 k16, both m-fragments share K B-fragments ----
        float sc[2][8][4];
#pragma unroll
        for (int nf = 0; nf < 8; nf++) {
#pragma unroll
            for (int i = 0; i < 4; i++) { sc[0][nf][i] = 0.f; sc[1][nf][i] = 0.f; }
#pragma unroll
            for (int kc = 0; kc < 4; kc++) {
                uint32_t b0 = Kpk[(nf * 8 + grp) * KPS + kc * 8 + t4];
                uint32_t b1 = Kpk[(nf * 8 + grp) * KPS + kc * 8 + 4 + t4];
                mma_fp16(sc[0][nf], qa[0][kc], b0, b1);
                mma_fp16(sc[1][nf], qa[1][kc], b0, b1);
            }
        }

        if (!allones) {
            asm volatile("cp.async.wait_group 0;");
            __syncthreads();
        }

        // ---- mask + online softmax per m-fragment ----
#pragma unroll
        for (int mf = 0; mf < 2; mf++) {
            int ra = r0 + mf * 16, rb = ra + 8;
            if (!allones) {
#pragma unroll
                for (int nf = 0; nf < 8; nf++) {
                    int2 ma = *(const int2*)&Mi[ra * AMS + nf * 8 + 2 * t4];
                    int2 mb = *(const int2*)&Mi[rb * AMS + nf * 8 + 2 * t4];
                    if (ma.x == 0) sc[mf][nf][0] = -1e9f;
                    if (ma.y == 0) sc[mf][nf][1] = -1e9f;
                    if (mb.x == 0) sc[mf][nf][2] = -1e9f;
                    if (mb.y == 0) sc[mf][nf][3] = -1e9f;
                }
            }
            float tma = -1e30f, tmb = -1e30f;
#pragma unroll
            for (int nf = 0; nf < 8; nf++) {
                tma = fmaxf(tma, fmaxf(sc[mf][nf][0], sc[mf][nf][1]));
                tmb = fmaxf(tmb, fmaxf(sc[mf][nf][2], sc[mf][nf][3]));
            }
            tma = fmaxf(tma, __shfl_xor_sync(0xffffffffu, tma, 1));
            tma = fmaxf(tma, __shfl_xor_sync(0xffffffffu, tma, 2));
            tmb = fmaxf(tmb, __shfl_xor_sync(0xffffffffu, tmb, 1));
            tmb = fmaxf(tmb, __shfl_xor_sync(0xffffffffu, tmb, 2));

            float mna = fmaxf(mrow[2 * mf], tma);
            float mnb = fmaxf(mrow[2 * mf + 1], tmb);
            float ala = __expf(mrow[2 * mf] - mna);
            float alb = __expf(mrow[2 * mf + 1] - mnb);
            mrow[2 * mf] = mna; mrow[2 * mf + 1] = mnb;

            float rsa = 0.f, rsb = 0.f;
#pragma unroll
            for (int nf = 0; nf < 8; nf++) {
                float p00 = __expf(sc[mf][nf][0] - mna);
                float p01 = __expf(sc[mf][nf][1] - mna);
                float p10 = __expf(sc[mf][nf][2] - mnb);
                float p11 = __expf(sc[mf][nf][3] - mnb);
                rsa += p00 + p01;
                rsb += p10 + p11;
                Ppk[ra * PPS + nf * 4 + t4] = f16pk(p00, p01);
                Ppk[rb * PPS + nf * 4 + t4] = f16pk(p10, p11);
                o[mf][nf][0] *= ala; o[mf][nf][1] *= ala;
                o[mf][nf][2] *= alb; o[mf][nf][3] *= alb;
            }
            rsa += __shfl_xor_sync(0xffffffffu, rsa, 1);
            rsa += __shfl_xor_sync(0xffffffffu, rsa, 2);
            rsb += __shfl_xor_sync(0xffffffffu, rsb, 1);
            rsb += __shfl_xor_sync(0xffffffffu, rsb, 2);
            lrow[2 * mf]     = lrow[2 * mf] * ala + rsa;
            lrow[2 * mf + 1] = lrow[2 * mf + 1] * alb + rsb;
        }
        __syncwarp();   // P round-trip is warp-local

        // ---- prefetch next K/V (sc regs now dead; PV below covers latency) ----
        if (t < 31) {
            const float* Kn = Kg + (size_t)(t + 1) * 64 * 64;
            const float* Vn = Vg + (size_t)(t + 1) * 64 * 64;
#pragma unroll
            for (int p = 0; p < 4; p++)
                kr[p] = *(const float4*)(Kn + (size_t)(p * 16 + kr_r) * 64 + kr_c);
#pragma unroll
            for (int p = 0; p < 2; p++) {
                int pr = p * 16 + kr_r;
                vra[p] = *(const float4*)(Vn + (size_t)(2 * pr) * 64 + kr_c);
                vrb[p] = *(const float4*)(Vn + (size_t)(2 * pr + 1) * 64 + kr_c);
            }
        }

        // ---- PV: fp16 k16, V B-fragments shared across the 2 m-fragments ----
#pragma unroll
        for (int kc = 0; kc < 4; kc++) {
            uint32_t pa[2][4];
#pragma unroll
            for (int mf = 0; mf < 2; mf++) {
                int ra = r0 + mf * 16, rb = ra + 8;
                pa[mf][0] = Ppk[ra * PPS + kc * 8 + t4];
                pa[mf][1] = Ppk[rb * PPS + kc * 8 + t4];
                pa[mf][2] = Ppk[ra * PPS + kc * 8 + 4 + t4];
                pa[mf][3] = Ppk[rb * PPS + kc * 8 + 4 + t4];
            }
#pragma unroll
            for (int nf = 0; nf < 8; nf++) {
                uint32_t b0 = Vpk[(kc * 8 + t4) * VPS + nf * 8 + grp];
                uint32_t b1 = Vpk[(kc * 8 + 4 + t4) * VPS + nf * 8 + grp];
                mma_fp16(o[0][nf], pa[0], b0, b1);
                mma_fp16(o[1][nf], pa[1], b0, b1);
            }
        }
    }

    // ---- finalize: O / l, write [B,S,D] ----
#pragma unroll
    for (int mf = 0; mf < 2; mf++) {
        float inva = 1.f / lrow[2 * mf];
        float invb = 1.f / lrow[2 * mf + 1];
        int ga = qblk * 256 + r0 + mf * 16;
        int gb = ga + 8;
        float* opa = out + ((size_t)b * S_ + ga) * D_ + h * 64;
        float* opb = out + ((size_t)b * S_ + gb) * D_ + h * 64;
#pragma unroll
        for (int nf = 0; nf < 8; nf++) {
            int cb = nf * 8 + 2 * t4;
            *(float2*)(opa + cb) = make_float2(o[mf][nf][0] * inva, o[mf][nf][1] * inva);
            *(float2*)(opb + cb) = make_float2(o[mf][nf][2] * invb, o[mf][nf][3] * invb);
        }
    }
}

// ---------------------------------------------------------------------------
// Launch
// Inputs (metadata order): query, key, value, mask, Wq, bq, Wk, bk, Wv, bv
// ---------------------------------------------------------------------------
extern "C" void kernel_launch(void* const* d_in, const int* in_sizes, int n_in,
                              void* d_out, int out_size)
{
    const float* query = (const float*)d_in[0];
    const float* key   = (const float*)d_in[1];
    const float* value = (const float*)d_in[2];
    const int*   mask  = (const int*)  d_in[3];
    const float* Wq    = (const float*)d_in[4];
    const float* bq    = (const float*)d_in[5];
    const float* Wk    = (const float*)d_in[6];
    const float* bk    = (const float*)d_in[7];
    const float* Wv    = (const float*)d_in[8];
    const float* bv    = (const float*)d_in[9];
    float* out = (float*)d_out;

    float *qptr, *kptr, *vptr;
    cudaGetSymbolAddress((void**)&qptr, g_Q);
    cudaGetSymbolAddress((void**)&kptr, g_K);
    cudaGetSymbolAddress((void**)&vptr, g_V);

    dim3 pgrid(8, 64);
    proj_tc<true ><<<pgrid, 256>>>(query, Wq, bq, qptr);
    proj_tc<false><<<pgrid, 256>>>(key,   Wk, bk, kptr);
    proj_tc<false><<<pgrid, 256>>>(value, Wv, bv, vptr);

    dim3 mgrid(32, 8, 4);
    mask_scan<<<mgrid, 256>>>(mask);

    const int smem_words = 64 * KPS + 32 * VPS + 256 * PPS + 256 * AMS;
    const int smem = smem_words * (int)sizeof(uint32_t);   // 124,928 B
    cudaFuncSetAttribute(attn_mma, cudaFuncAttributeMaxDynamicSharedMemorySize, smem);

    dim3 agrid(8, 64);   // 256-row q tiles, B*H
    attn_mma<<<agrid, 256, smem>>>(mask, out);
}

// round 7
// speedup vs baseline: 15.2087x; 1.0258x over previous
#include <cuda_runtime.h>
#include <cuda_fp16.h>
#include <cstdint>
#include <math.h>

// Problem constants
#define B_  4
#define S_  2048
#define D_  1024
#define H_  16
#define DK_ 64

// Scratch (device globals — no allocs)
__device__ float g_Q[(size_t)B_ * H_ * S_ * DK_];
__device__ float g_K[(size_t)B_ * H_ * S_ * DK_];
__device__ float g_V[(size_t)B_ * H_ * S_ * DK_];
__device__ int g_mflag[B_ * 8 * 32];
// pre-converted bf16 hi/lo planes (packed pairs along k: word = 2 bf16)
__device__ uint32_t g_Xhi[(size_t)3 * 8192 * 512];
__device__ uint32_t g_Xlo[(size_t)3 * 8192 * 512];
__device__ uint32_t g_Whi[(size_t)3 * 1024 * 512];
__device__ uint32_t g_Wlo[(size_t)3 * 1024 * 512];

// ---------------------------------------------------------------------------
// helpers
// ---------------------------------------------------------------------------
__device__ __forceinline__ void cvt_hilo(float x0, float x1, uint32_t& hi, uint32_t& lo)
{
    uint32_t h;
    asm("cvt.rn.bf16x2.f32 %0, %1, %2;" : "=r"(h) : "f"(x1), "f"(x0));
    float h0 = __uint_as_float(h << 16);
    float h1 = __uint_as_float(h & 0xffff0000u);
    float l0 = x0 - h0;
    float l1 = x1 - h1;
    uint32_t l;
    asm("cvt.rn.bf16x2.f32 %0, %1, %2;" : "=r"(l) : "f"(l1), "f"(l0));
    hi = h; lo = l;
}

__device__ __forceinline__ void mma_bf16(float* d, const uint32_t* a,
                                         uint32_t b0, uint32_t b1)
{
    asm volatile(
        "mma.sync.aligned.m16n8k16.row.col.f32.bf16.bf16.f32 "
        "{%0,%1,%2,%3},{%4,%5,%6,%7},{%8,%9},{%0,%1,%2,%3};"
        : "+f"(d[0]), "+f"(d[1]), "+f"(d[2]), "+f"(d[3])
        : "r"(a[0]), "r"(a[1]), "r"(a[2]), "r"(a[3]), "r"(b0), "r"(b1));
}

__device__ __forceinline__ void cp_async16(uint32_t dst_smem, const void* src) {
    asm volatile("cp.async.cg.shared.global [%0], [%1], 16;"
                 :: "r"(dst_smem), "l"(src));
}

// ---------------------------------------------------------------------------
// Prep: fp32 -> bf16 hi/lo planes (one pass; removes per-CTA re-conversion)
// ---------------------------------------------------------------------------
__global__ __launch_bounds__(256)
void prep_x(const float* __restrict__ q, const float* __restrict__ k,
            const float* __restrict__ v)
{
    const int z = blockIdx.z;
    const float* src = (z == 0) ? q : (z == 1) ? k : v;
    size_t idx = (size_t)blockIdx.x * 256 + threadIdx.x;   // float4 index
    float4 xv = *((const float4*)src + idx);
    uint32_t h0, l0, h1, l1;
    cvt_hilo(xv.x, xv.y, h0, l0);
    cvt_hilo(xv.z, xv.w, h1, l1);
    size_t w = (size_t)z * 8192 * 512 + idx * 2;
    *(uint2*)&g_Xhi[w] = make_uint2(h0, h1);
    *(uint2*)&g_Xlo[w] = make_uint2(l0, l1);
}

__global__ __launch_bounds__(256)
void prep_w(const float* __restrict__ wq, const float* __restrict__ wk,
            const float* __restrict__ wv)
{
    const int z = blockIdx.z;
    const float* src = (z == 0) ? wq : (z == 1) ? wk : wv;
    size_t idx = (size_t)blockIdx.x * 256 + threadIdx.x;
    float4 xv = *((const float4*)src + idx);
    uint32_t h0, l0, h1, l1;
    cvt_hilo(xv.x, xv.y, h0, l0);
    cvt_hilo(xv.z, xv.w, h1, l1);
    size_t w = (size_t)z * 1024 * 512 + idx * 2;
    *(uint2*)&g_Whi[w] = make_uint2(h0, h1);
    *(uint2*)&g_Wlo[w] = make_uint2(l0, l1);
}

// ---------------------------------------------------------------------------
// Fused projection GEMM, bf16x3, cp.async double buffered.
// grid (8, 64, 3): z selects (X, W, bias, out). CTA tile 128x128x32,
// 8 warps (2x4), warp tile 64x32. smem: 2 buffers x 4 planes x 128x20 words.
// ---------------------------------------------------------------------------
#define PSTRIDE 20
#define PLANE_W (128 * PSTRIDE)        // 2560 words per plane
#define BUF_W   (4 * PLANE_W)          // 10240 words per buffer

__global__ __launch_bounds__(256, 2)
void proj_gemm(const float* __restrict__ bq, const float* __restrict__ bk,
               const float* __restrict__ bv,
               float* __restrict__ oq, float* __restrict__ ok_,
               float* __restrict__ ov)
{
    extern __shared__ uint32_t sbuf[];   // 2 * BUF_W words

    const int tid  = threadIdx.x;
    const int warp = tid >> 5;
    const int lane = tid & 31;
    const int grp  = lane >> 2;
    const int t4   = lane & 3;
    const int bm   = blockIdx.y;
    const int bn   = blockIdx.x;
    const int z    = blockIdx.z;
    const int wm   = (warp >> 2) * 64;
    const int wn   = (warp & 3) * 32;

    const float* bias = (z == 0) ? bq : (z == 1) ? bk : bv;
    float* out        = (z == 0) ? oq : (z == 1) ? ok_ : ov;
    const bool scale  = (z == 0);

    const uint32_t* xhi = g_Xhi + (size_t)z * 8192 * 512 + (size_t)(bm * 128) * 512;
    const uint32_t* xlo = g_Xlo + (size_t)z * 8192 * 512 + (size_t)(bm * 128) * 512;
    const uint32_t* whi = g_Whi + (size_t)z * 1024 * 512 + (size_t)(bn * 128) * 512;
    const uint32_t* wlo = g_Wlo + (size_t)z * 1024 * 512 + (size_t)(bn * 128) * 512;
    const uint32_t* planes[4] = {xhi, xlo, whi, wlo};

    // issue one k-tile (32 bf16 = 16 words per row) into buffer `dst`
    auto issue = [&](int ks, uint32_t* dst) {
#pragma unroll
        for (int i = 0; i < 8; i++) {
            const int plane = i >> 1;                       // compile-time
            const int row = (i & 1) * 64 + (tid >> 2);      // 0..127
            const int w4 = (t4) * 4;                        // word offset 0/4/8/12
            uint32_t daddr = (uint32_t)__cvta_generic_to_shared(
                dst + plane * PLANE_W + row * PSTRIDE + w4);
            cp_async16(daddr, planes[plane] + (size_t)row * 512 + ks * 16 + w4);
        }
        asm volatile("cp.async.commit_group;");
    };

    float acc[4][4][4];
#pragma unroll
    for (int mf = 0; mf < 4; mf++)
#pragma unroll
        for (int nf = 0; nf < 4; nf++)
#pragma unroll
            for (int i = 0; i < 4; i++) acc[mf][nf][i] = 0.f;

    issue(0, sbuf);

    for (int ks = 0; ks < 32; ks++) {
        uint32_t* cur = sbuf + (ks & 1) * BUF_W;
        if (ks < 31) {
            issue(ks + 1, sbuf + ((ks + 1) & 1) * BUF_W);
            asm volatile("cp.async.wait_group 1;");
        } else {
            asm volatile("cp.async.wait_group 0;");
        }
        __syncthreads();

        const uint32_t* sXhi = cur;
        const uint32_t* sXlo = cur + PLANE_W;
        const uint32_t* sWhi = cur + 2 * PLANE_W;
        const uint32_t* sWlo = cur + 3 * PLANE_W;

#pragma unroll
        for (int kc = 0; kc < 2; kc++) {
            const int kp = kc * 8 + t4;
            uint32_t ah[4][4], al[4][4];
#pragma unroll
            for (int mf = 0; mf < 4; mf++) {
                int r0 = wm + mf * 16 + grp;
                ah[mf][0] = sXhi[r0 * PSTRIDE + kp];
                ah[mf][1] = sXhi[(r0 + 8) * PSTRIDE + kp];
                ah[mf][2] = sXhi[r0 * PSTRIDE + kp + 4];
                ah[mf][3] = sXhi[(r0 + 8) * PSTRIDE + kp + 4];
                al[mf][0] = sXlo[r0 * PSTRIDE + kp];
                al[mf][1] = sXlo[(r0 + 8) * PSTRIDE + kp];
                al[mf][2] = sXlo[r0 * PSTRIDE + kp + 4];
                al[mf][3] = sXlo[(r0 + 8) * PSTRIDE + kp + 4];
            }
#pragma unroll
            for (int nf = 0; nf < 4; nf++) {
                int n = wn + nf * 8 + grp;
                uint32_t bh0 = sWhi[n * PSTRIDE + kp];
                uint32_t bh1 = sWhi[n * PSTRIDE + kp + 4];
                uint32_t bl0 = sWlo[n * PSTRIDE + kp];
                uint32_t bl1 = sWlo[n * PSTRIDE + kp + 4];
#pragma unroll
                for (int mf = 0; mf < 4; mf++) {
                    mma_bf16(acc[mf][nf], ah[mf], bh0, bh1);
                    mma_bf16(acc[mf][nf], ah[mf], bl0, bl1);
                    mma_bf16(acc[mf][nf], al[mf], bh0, bh1);
                }
            }
        }
        __syncthreads();
    }

    // Epilogue: bias, optional scale, scatter into [B,H,S,DK]
#pragma unroll
    for (int mf = 0; mf < 4; mf++) {
        int row0 = bm * 128 + wm + mf * 16 + grp;
        int row1 = row0 + 8;
        int b0i = row0 >> 11, s0 = row0 & 2047;
        int b1i = row1 >> 11, s1 = row1 & 2047;
#pragma unroll
        for (int nf = 0; nf < 4; nf++) {
            int col = bn * 128 + wn + nf * 8 + 2 * t4;
            int h = col >> 6;
            int d = col & 63;
            float bb0 = bias[col], bb1 = bias[col + 1];
            float v00 = acc[mf][nf][0] + bb0;
            float v01 = acc[mf][nf][1] + bb1;
            float v10 = acc[mf][nf][2] + bb0;
            float v11 = acc[mf][nf][3] + bb1;
            if (scale) { v00 *= 0.125f; v01 *= 0.125f; v10 *= 0.125f; v11 *= 0.125f; }
            *(float2*)&out[(((size_t)(b0i * H_ + h) * S_) + s0) * DK_ + d] = make_float2(v00, v01);
            *(float2*)&out[(((size_t)(b1i * H_ + h) * S_) + s1) * DK_ + d] = make_float2(v10, v11);
        }
    }
}

// ---------------------------------------------------------------------------
// Mask scan: flag[b][qt][kt] = 1 iff mask[b, qt*256:+256, kt*64:+64] all nonzero
// ---------------------------------------------------------------------------
__global__ void mask_scan(const int* __restrict__ mask)
{
    const int kt = blockIdx.x;
    const int qt = blockIdx.y;
    const int b  = blockIdx.z;
    const int* rp = mask + ((size_t)b * S_ + qt * 256 + threadIdx.x) * S_ + kt * 64;
    int ok = 1;
#pragma unroll
    for (int c = 0; c < 64; c += 4) {
        int4 v = *(const int4*)(rp + c);
        ok &= (v.x != 0) & (v.y != 0) & (v.z != 0) & (v.w != 0);
    }
    ok = __syncthreads_and(ok);
    if (threadIdx.x == 0) g_mflag[(b * 8 + qt) * 32 + kt] = ok;
}

// ---------------------------------------------------------------------------
// FP16 mma helper (attention)
// ---------------------------------------------------------------------------
__device__ __forceinline__ void mma_fp16(float* d, const uint32_t* a,
                                         uint32_t b0, uint32_t b1)
{
    asm volatile(
        "mma.sync.aligned.m16n8k16.row.col.f32.f16.f16.f32 "
        "{%0,%1,%2,%3},{%4,%5,%6,%7},{%8,%9},{%0,%1,%2,%3};"
        : "+f"(d[0]), "+f"(d[1]), "+f"(d[2]), "+f"(d[3])
        : "r"(a[0]), "r"(a[1]), "r"(a[2]), "r"(a[3]), "r"(b0), "r"(b1));
}

__device__ __forceinline__ uint32_t f16pk(float x0, float x1) {
    __half2 h = __floats2half2_rn(x0, x1);
    return *(uint32_t*)&h;
}

// ---------------------------------------------------------------------------
// Flash attention, FP16 m16n8k16, mf=2 warp tiling, mask elision
// (unchanged from round 6 — proven at ~310us).
// ---------------------------------------------------------------------------
#define KPS 36
#define VPS 72
#define PPS 36
#define AMS 68

__global__ __launch_bounds__(256, 1)
void attn_mma(const int* __restrict__ mask, float* __restrict__ out)
{
    extern __shared__ uint32_t smu[];
    uint32_t* Kpk = smu;
    uint32_t* Vpk = Kpk + 64 * KPS;
    uint32_t* Ppk = Vpk + 32 * VPS;
    int*      Mi  = (int*)(Ppk + 256 * PPS);

    const int tid  = threadIdx.x;
    const int warp = tid >> 5;
    const int lane = tid & 31;
    const int grp  = lane >> 2;
    const int t4   = lane & 3;

    const int qblk = blockIdx.x;
    const int bh   = blockIdx.y;
    const int b    = bh >> 4;
    const int h    = bh & 15;

    const float* Qg = g_Q + (size_t)bh * S_ * DK_ + (size_t)qblk * 256 * DK_;
    const float* Kg = g_K + (size_t)bh * S_ * DK_;
    const float* Vg = g_V + (size_t)bh * S_ * DK_;
    const int* maskg = mask + (size_t)b * S_ * S_ + (size_t)(qblk * 256) * S_;
    const int* mfl = g_mflag + (b * 8 + qblk) * 32;

    const int r0 = warp * 32 + grp;

    {
        float* Qs = (float*)Mi;
#pragma unroll
        for (int p = 0; p < 16; p++) {
            int idx = p * 256 + tid;
            int r = idx >> 4;
            int c = (idx & 15) * 4;
            *(float4*)&Qs[r * AMS + c] = *(const float4*)(Qg + (size_t)r * 64 + c);
        }
    }
    __syncthreads();

    uint32_t qa[2][4][4];
    {
        const float* Qs = (const float*)Mi;
#pragma unroll
        for (int mf = 0; mf < 2; mf++) {
            int ra = r0 + mf * 16, rb = ra + 8;
#pragma unroll
            for (int kc = 0; kc < 4; kc++) {
                int c = kc * 16 + 2 * t4;
                qa[mf][kc][0] = f16pk(Qs[ra * AMS + c],     Qs[ra * AMS + c + 1]);
                qa[mf][kc][1] = f16pk(Qs[rb * AMS + c],     Qs[rb * AMS + c + 1]);
                qa[mf][kc][2] = f16pk(Qs[ra * AMS + c + 8], Qs[ra * AMS + c + 9]);
                qa[mf][kc][3] = f16pk(Qs[rb * AMS + c + 8], Qs[rb * AMS + c + 9]);
            }
        }
    }
    __syncthreads();

    float o[2][8][4];
#pragma unroll
    for (int mf = 0; mf < 2; mf++)
#pragma unroll
        for (int nf = 0; nf < 8; nf++)
#pragma unroll
            for (int i = 0; i < 4; i++) o[mf][nf][i] = 0.f;

    float mrow[4] = {-1e30f, -1e30f, -1e30f, -1e30f};
    float lrow[4] = {0.f, 0.f, 0.f, 0.f};

    const int kr_r = tid >> 4;
    const int kr_c = (tid & 15) * 4;

    float4 kr[4], vra[2], vrb[2];
#pragma unroll
    for (int p = 0; p < 4; p++)
        kr[p] = *(const float4*)(Kg + (size_t)(p * 16 + kr_r) * 64 + kr_c);
#pragma unroll
    for (int p = 0; p < 2; p++) {
        int pr = p * 16 + kr_r;
        vra[p] = *(const float4*)(Vg + (size_t)(2 * pr) * 64 + kr_c);
        vrb[p] = *(const float4*)(Vg + (size_t)(2 * pr + 1) * 64 + kr_c);
    }

    for (int t = 0; t < 32; t++) {
        const int allones = mfl[t];
        if (t) __syncthreads();

#pragma unroll
        for (int p = 0; p < 4; p++) {
            int r = p * 16 + kr_r;
            *(uint2*)&Kpk[r * KPS + (kr_c >> 1)] =
                make_uint2(f16pk(kr[p].x, kr[p].y), f16pk(kr[p].z, kr[p].w));
        }
#pragma unroll
        for (int p = 0; p < 2; p++) {
            int pr = p * 16 + kr_r;
            *(uint4*)&Vpk[pr * VPS + kr_c] =
                make_uint4(f16pk(vra[p].x, vrb[p].x), f16pk(vra[p].y, vrb[p].y),
                           f16pk(vra[p].z, vrb[p].z), f16pk(vra[p].w, vrb[p].w));
        }
        if (!allones) {
#pragma unroll
            for (int p = 0; p < 16; p++) {
                int idx = p * 256 + tid;
                int r = idx >> 4;
                int c4 = (idx & 15) * 4;
                uint32_t dst = (uint32_t)__cvta_generic_to_shared(&Mi[r * AMS + c4]);
                cp_async16(dst, maskg + (size_t)r * S_ + t * 64 + c4);
            }
            asm volatile("cp.async.commit_group;");
        }
        __syncthreads();

        float sc[2][8][4];
#pragma unroll
        for (int nf = 0; nf < 8; nf++) {
#pragma unroll
            for (int i = 0; i < 4; i++) { sc[0][nf][i] = 0.f; sc[1][nf][i] = 0.f; }
#pragma unroll
            for (int kc = 0; kc < 4; kc++) {
                uint32_t b0 = Kpk[(nf * 8 + grp) * KPS + kc * 8 + t4];
                uint32_t b1 = Kpk[(nf * 8 + grp) * KPS + kc * 8 + 4 + t4];
                mma_fp16(sc[0][nf], qa[0][kc], b0, b1);
                mma_fp16(sc[1][nf], qa[1][kc], b0, b1);
            }
        }

        if (!allones) {
            asm volatile("cp.async.wait_group 0;");
            __syncthreads();
        }

#pragma unroll
        for (int mf = 0; mf < 2; mf++) {
            int ra = r0 + mf * 16, rb = ra + 8;
            if (!allones) {
#pragma unroll
                for (int nf = 0; nf < 8; nf++) {
                    int2 ma = *(const int2*)&Mi[ra * AMS + nf * 8 + 2 * t4];
                    int2 mb = *(const int2*)&Mi[rb * AMS + nf * 8 + 2 * t4];
                    if (ma.x == 0) sc[mf][nf][0] = -1e9f;
                    if (ma.y == 0) sc[mf][nf][1] = -1e9f;
                    if (mb.x == 0) sc[mf][nf][2] = -1e9f;
                    if (mb.y == 0) sc[mf][nf][3] = -1e9f;
                }
            }
            float tma = -1e30f, tmb = -1e30f;
#pragma unroll
            for (int nf = 0; nf < 8; nf++) {
                tma = fmaxf(tma, fmaxf(sc[mf][nf][0], sc[mf][nf][1]));
                tmb = fmaxf(tmb, fmaxf(sc[mf][nf][2], sc[mf][nf][3]));
            }
            tma = fmaxf(tma, __shfl_xor_sync(0xffffffffu, tma, 1));
            tma = fmaxf(tma, __shfl_xor_sync(0xffffffffu, tma, 2));
            tmb = fmaxf(tmb, __shfl_xor_sync(0xffffffffu, tmb, 1));
            tmb = fmaxf(tmb, __shfl_xor_sync(0xffffffffu, tmb, 2));

            float mna = fmaxf(mrow[2 * mf], tma);
            float mnb = fmaxf(mrow[2 * mf + 1], tmb);
            float ala = __expf(mrow[2 * mf] - mna);
            float alb = __expf(mrow[2 * mf + 1] - mnb);
            mrow[2 * mf] = mna; mrow[2 * mf + 1] = mnb;

            float rsa = 0.f, rsb = 0.f;
#pragma unroll
            for (int nf = 0; nf < 8; nf++) {
                float p00 = __expf(sc[mf][nf][0] - mna);
                float p01 = __expf(sc[mf][nf][1] - mna);
                float p10 = __expf(sc[mf][nf][2] - mnb);
                float p11 = __expf(sc[mf][nf][3] - mnb);
                rsa += p00 + p01;
                rsb += p10 + p11;
                Ppk[ra * PPS + nf * 4 + t4] = f16pk(p00, p01);
                Ppk[rb * PPS + nf * 4 + t4] = f16pk(p10, p11);
                o[mf][nf][0] *= ala; o[mf][nf][1] *= ala;
                o[mf][nf][2] *= alb; o[mf][nf][3] *= alb;
            }
            rsa += __shfl_xor_sync(0xffffffffu, rsa, 1);
            rsa += __shfl_xor_sync(0xffffffffu, rsa, 2);
            rsb += __shfl_xor_sync(0xffffffffu, rsb, 1);
            rsb += __shfl_xor_sync(0xffffffffu, rsb, 2);
            lrow[2 * mf]     = lrow[2 * mf] * ala + rsa;
            lrow[2 * mf + 1] = lrow[2 * mf + 1] * alb + rsb;
        }
        __syncwarp();

        if (t < 31) {
            const float* Kn = Kg + (size_t)(t + 1) * 64 * 64;
            const float* Vn = Vg + (size_t)(t + 1) * 64 * 64;
#pragma unroll
            for (int p = 0; p < 4; p++)
                kr[p] = *(const float4*)(Kn + (size_t)(p * 16 + kr_r) * 64 + kr_c);
#pragma unroll
            for (int p = 0; p < 2; p++) {
                int pr = p * 16 + kr_r;
                vra[p] = *(const float4*)(Vn + (size_t)(2 * pr) * 64 + kr_c);
                vrb[p] = *(const float4*)(Vn + (size_t)(2 * pr + 1) * 64 + kr_c);
            }
        }

#pragma unroll
        for (int kc = 0; kc < 4; kc++) {
            uint32_t pa[2][4];
#pragma unroll
            for (int mf = 0; mf < 2; mf++) {
                int ra = r0 + mf * 16, rb = ra + 8;
                pa[mf][0] = Ppk[ra * PPS + kc * 8 + t4];
                pa[mf][1] = Ppk[rb * PPS + kc * 8 + t4];
                pa[mf][2] = Ppk[ra * PPS + kc * 8 + 4 + t4];
                pa[mf][3] = Ppk[rb * PPS + kc * 8 + 4 + t4];
            }
#pragma unroll
            for (int nf = 0; nf < 8; nf++) {
                uint32_t b0 = Vpk[(kc * 8 + t4) * VPS + nf * 8 + grp];
                uint32_t b1 = Vpk[(kc * 8 + 4 + t4) * VPS + nf * 8 + grp];
                mma_fp16(o[0][nf], pa[0], b0, b1);
                mma_fp16(o[1][nf], pa[1], b0, b1);
            }
        }
    }

#pragma unroll
    for (int mf = 0; mf < 2; mf++) {
        float inva = 1.f / lrow[2 * mf];
        float invb = 1.f / lrow[2 * mf + 1];
        int ga = qblk * 256 + r0 + mf * 16;
        int gb = ga + 8;
        float* opa = out + ((size_t)b * S_ + ga) * D_ + h * 64;
        float* opb = out + ((size_t)b * S_ + gb) * D_ + h * 64;
#pragma unroll
        for (int nf = 0; nf < 8; nf++) {
            int cb = nf * 8 + 2 * t4;
            *(float2*)(opa + cb) = make_float2(o[mf][nf][0] * inva, o[mf][nf][1] * inva);
            *(float2*)(opb + cb) = make_float2(o[mf][nf][2] * invb, o[mf][nf][3] * invb);
        }
    }
}

// ---------------------------------------------------------------------------
// Launch
// Inputs (metadata order): query, key, value, mask, Wq, bq, Wk, bk, Wv, bv
// ---------------------------------------------------------------------------
extern "C" void kernel_launch(void* const* d_in, const int* in_sizes, int n_in,
                              void* d_out, int out_size)
{
    const float* query = (const float*)d_in[0];
    const float* key   = (const float*)d_in[1];
    const float* value = (const float*)d_in[2];
    const int*   mask  = (const int*)  d_in[3];
    const float* Wq    = (const float*)d_in[4];
    const float* bq    = (const float*)d_in[5];
    const float* Wk    = (const float*)d_in[6];
    const float* bk    = (const float*)d_in[7];
    const float* Wv    = (const float*)d_in[8];
    const float* bv    = (const float*)d_in[9];
    float* out = (float*)d_out;

    float *qptr, *kptr, *vptr;
    cudaGetSymbolAddress((void**)&qptr, g_Q);
    cudaGetSymbolAddress((void**)&kptr, g_K);
    cudaGetSymbolAddress((void**)&vptr, g_V);

    // prep: fp32 -> bf16 hi/lo planes
    prep_x<<<dim3(8192, 1, 3), 256>>>(query, key, value);
    prep_w<<<dim3(1024, 1, 3), 256>>>(Wq, Wk, Wv);
    mask_scan<<<dim3(32, 8, 4), 256>>>(mask);

    // fused projections
    const int psmem = 2 * BUF_W * (int)sizeof(uint32_t);   // 81,920 B
    cudaFuncSetAttribute(proj_gemm, cudaFuncAttributeMaxDynamicSharedMemorySize, psmem);
    proj_gemm<<<dim3(8, 64, 3), 256, psmem>>>(bq, bk, bv, qptr, kptr, vptr);

    // attention
    const int asmem = (64 * KPS + 32 * VPS + 256 * PPS + 256 * AMS) * (int)sizeof(uint32_t);
    cudaFuncSetAttribute(attn_mma, cudaFuncAttributeMaxDynamicSharedMemorySize, asmem);
    attn_mma<<<dim3(8, 64), 256, asmem>>>(mask, out);
}

// round 9
// speedup vs baseline: 23.6422x; 1.5545x over previous
#include <cuda_runtime.h>
#include <cuda_fp16.h>
#include <cstdint>
#include <math.h>

// Problem constants
#define B_  4
#define S_  2048
#define D_  1024
#define H_  16
#define DK_ 64

// Scratch (device globals — no allocs)
__device__ float g_Q[(size_t)B_ * H_ * S_ * DK_];
__device__ float g_K[(size_t)B_ * H_ * S_ * DK_];
__device__ float g_V[(size_t)B_ * H_ * S_ * DK_];
__device__ int g_mflag[B_ * 8 * 32];
// pre-converted fp16 planes (packed pairs along k: one word = 2 fp16)
__device__ uint32_t g_Xpk[(size_t)3 * 8192 * 512];
__device__ uint32_t g_Wpk[(size_t)3 * 1024 * 512];

// ---------------------------------------------------------------------------
// helpers
// ---------------------------------------------------------------------------
__device__ __forceinline__ uint32_t f16pk(float x0, float x1) {
    __half2 h = __floats2half2_rn(x0, x1);
    return *(uint32_t*)&h;
}

__device__ __forceinline__ void mma_fp16(float* d, const uint32_t* a,
                                         uint32_t b0, uint32_t b1)
{
    asm volatile(
        "mma.sync.aligned.m16n8k16.row.col.f32.f16.f16.f32 "
        "{%0,%1,%2,%3},{%4,%5,%6,%7},{%8,%9},{%0,%1,%2,%3};"
        : "+f"(d[0]), "+f"(d[1]), "+f"(d[2]), "+f"(d[3])
        : "r"(a[0]), "r"(a[1]), "r"(a[2]), "r"(a[3]), "r"(b0), "r"(b1));
}

__device__ __forceinline__ void cp_async16(uint32_t dst_smem, const void* src) {
    asm volatile("cp.async.cg.shared.global [%0], [%1], 16;"
                 :: "r"(dst_smem), "l"(src));
}

// ---------------------------------------------------------------------------
// Prep: fp32 -> packed fp16 planes (one pass)
// ---------------------------------------------------------------------------
__global__ __launch_bounds__(256)
void prep_x(const float* __restrict__ q, const float* __restrict__ k,
            const float* __restrict__ v)
{
    const int z = blockIdx.z;
    const int m = blockIdx.x;            // 0..8191
    const int kq = threadIdx.x;          // 0..255 (float4 index)
    const float* src = (z == 0) ? q : (z == 1) ? k : v;
    float4 xv = *((const float4*)(src + (size_t)m * 1024) + kq);
    size_t w = ((size_t)z * 8192 + m) * 512 + kq * 2;
    *(uint2*)&g_Xpk[w] = make_uint2(f16pk(xv.x, xv.y), f16pk(xv.z, xv.w));
}

__global__ __launch_bounds__(256)
void prep_w(const float* __restrict__ wq, const float* __restrict__ wk,
            const float* __restrict__ wv)
{
    const int z = blockIdx.z;
    const int n = blockIdx.x;            // 0..1023
    const int kq = threadIdx.x;
    const float* src = (z == 0) ? wq : (z == 1) ? wk : wv;
    float4 xv = *((const float4*)(src + (size_t)n * 1024) + kq);
    size_t w = ((size_t)z * 1024 + n) * 512 + kq * 2;
    *(uint2*)&g_Wpk[w] = make_uint2(f16pk(xv.x, xv.y), f16pk(xv.z, xv.w));
}

// ---------------------------------------------------------------------------
// Fused projection GEMM, fp16 m16n8k16 (fp32 accum), cp.async double buffered.
// grid (8, 64, 3): z selects (X, W, bias, out). CTA tile 128x128x64,
// 8 warps (2x4), warp tile 64x32. smem: 2 buffers x (A + B) x 128x36 words.
// ---------------------------------------------------------------------------
#define PST 36
#define PLW (128 * PST)      // 4608 words per plane
#define BUFW (2 * PLW)       // 9216 words per buffer

__global__ __launch_bounds__(256, 2)
void proj_gemm(const float* __restrict__ bq, const float* __restrict__ bk,
               const float* __restrict__ bv,
               float* __restrict__ oq, float* __restrict__ ok_,
               float* __restrict__ ov)
{
    extern __shared__ uint32_t sbuf[];   // 2 * BUFW words

    const int tid  = threadIdx.x;
    const int warp = tid >> 5;
    const int lane = tid & 31;
    const int grp  = lane >> 2;
    const int t4   = lane & 3;
    const int bm   = blockIdx.y;
    const int bn   = blockIdx.x;
    const int z    = blockIdx.z;
    const int wm   = (warp >> 2) * 64;
    const int wn   = (warp & 3) * 32;

    const float* bias = (z == 0) ? bq : (z == 1) ? bk : bv;
    float* out        = (z == 0) ? oq : (z == 1) ? ok_ : ov;
    const bool scale  = (z == 0);

    const uint32_t* xpk = g_Xpk + ((size_t)z * 8192 + bm * 128) * 512;
    const uint32_t* wpk = g_Wpk + ((size_t)z * 1024 + bn * 128) * 512;

    // issue one k64-tile (32 words per row per plane) into buffer sel
    auto issue = [&](int kt, int sel) {
        uint32_t* dst = sbuf + sel * BUFW;
#pragma unroll
        for (int q = 0; q < 4; q++) {
            int idx = q * 256 + tid;          // 0..1023
            int r = idx >> 3;                 // 0..127
            int g4 = (idx & 7) * 4;           // word group
            uint32_t dA = (uint32_t)__cvta_generic_to_shared(dst + r * PST + g4);
            uint32_t dB = (uint32_t)__cvta_generic_to_shared(dst + PLW + r * PST + g4);
            cp_async16(dA, xpk + (size_t)r * 512 + kt * 32 + g4);
            cp_async16(dB, wpk + (size_t)r * 512 + kt * 32 + g4);
        }
        asm volatile("cp.async.commit_group;");
    };

    float acc[4][4][4];
#pragma unroll
    for (int mf = 0; mf < 4; mf++)
#pragma unroll
        for (int nf = 0; nf < 4; nf++)
#pragma unroll
            for (int i = 0; i < 4; i++) acc[mf][nf][i] = 0.f;

    issue(0, 0);

    for (int ks = 0; ks < 16; ks++) {
        const uint32_t* cur = sbuf + (ks & 1) * BUFW;
        if (ks < 15) {
            issue(ks + 1, (ks + 1) & 1);
            asm volatile("cp.async.wait_group 1;");
        } else {
            asm volatile("cp.async.wait_group 0;");
        }
        __syncthreads();

        const uint32_t* sA = cur;
        const uint32_t* sB = cur + PLW;

#pragma unroll
        for (int kc = 0; kc < 4; kc++) {
            const int kp = kc * 8 + t4;
            uint32_t ah[4][4];
#pragma unroll
            for (int mf = 0; mf < 4; mf++) {
                int r0 = wm + mf * 16 + grp;
                ah[mf][0] = sA[r0 * PST + kp];
                ah[mf][1] = sA[(r0 + 8) * PST + kp];
                ah[mf][2] = sA[r0 * PST + kp + 4];
                ah[mf][3] = sA[(r0 + 8) * PST + kp + 4];
            }
#pragma unroll
            for (int nf = 0; nf < 4; nf++) {
                int n = wn + nf * 8 + grp;
                uint32_t b0 = sB[n * PST + kp];
                uint32_t b1 = sB[n * PST + kp + 4];
#pragma unroll
                for (int mf = 0; mf < 4; mf++)
                    mma_fp16(acc[mf][nf], ah[mf], b0, b1);
            }
        }
        __syncthreads();
    }

    // Epilogue: bias, optional scale, scatter into [B,H,S,DK]
#pragma unroll
    for (int mf = 0; mf < 4; mf++) {
        int row0 = bm * 128 + wm + mf * 16 + grp;
        int row1 = row0 + 8;
        int b0i = row0 >> 11, s0 = row0 & 2047;
        int b1i = row1 >> 11, s1 = row1 & 2047;
#pragma unroll
        for (int nf = 0; nf < 4; nf++) {
            int col = bn * 128 + wn + nf * 8 + 2 * t4;
            int h = col >> 6;
            int d = col & 63;
            float bb0 = bias[col], bb1 = bias[col + 1];
            float v00 = acc[mf][nf][0] + bb0;
            float v01 = acc[mf][nf][1] + bb1;
            float v10 = acc[mf][nf][2] + bb0;
            float v11 = acc[mf][nf][3] + bb1;
            if (scale) { v00 *= 0.125f; v01 *= 0.125f; v10 *= 0.125f; v11 *= 0.125f; }
            *(float2*)&out[(((size_t)(b0i * H_ + h) * S_) + s0) * DK_ + d] = make_float2(v00, v01);
            *(float2*)&out[(((size_t)(b1i * H_ + h) * S_) + s1) * DK_ + d] = make_float2(v10, v11);
        }
    }
}

// ---------------------------------------------------------------------------
// Mask scan: flag[b][qt][kt] = 1 iff mask[b, qt*256:+256, kt*64:+64] all nonzero
// ---------------------------------------------------------------------------
__global__ void mask_scan(const int* __restrict__ mask)
{
    const int kt = blockIdx.x;
    const int qt = blockIdx.y;
    const int b  = blockIdx.z;
    const int* rp = mask + ((size_t)b * S_ + qt * 256 + threadIdx.x) * S_ + kt * 64;
    int ok = 1;
#pragma unroll
    for (int c = 0; c < 64; c += 4) {
        int4 v = *(const int4*)(rp + c);
        ok &= (v.x != 0) & (v.y != 0) & (v.z != 0) & (v.w != 0);
    }
    ok = __syncthreads_and(ok);
    if (threadIdx.x == 0) g_mflag[(b * 8 + qt) * 32 + kt] = ok;
}

// ---------------------------------------------------------------------------
// Flash attention, FP16 m16n8k16, mf=2 warp tiling, mask elision
// (unchanged — proven ~310us).
// ---------------------------------------------------------------------------
#define KPS 36
#define VPS 72
#define PPS 36
#define AMS 68

__global__ __launch_bounds__(256, 1)
void attn_mma(const int* __restrict__ mask, float* __restrict__ out)
{
    extern __shared__ uint32_t smu[];
    uint32_t* Kpk = smu;
    uint32_t* Vpk = Kpk + 64 * KPS;
    uint32_t* Ppk = Vpk + 32 * VPS;
    int*      Mi  = (int*)(Ppk + 256 * PPS);

    const int tid  = threadIdx.x;
    const int warp = tid >> 5;
    const int lane = tid & 31;
    const int grp  = lane >> 2;
    const int t4   = lane & 3;

    const int qblk = blockIdx.x;
    const int bh   = blockIdx.y;
    const int b    = bh >> 4;
    const int h    = bh & 15;

    const float* Qg = g_Q + (size_t)bh * S_ * DK_ + (size_t)qblk * 256 * DK_;
    const float* Kg = g_K + (size_t)bh * S_ * DK_;
    const float* Vg = g_V + (size_t)bh * S_ * DK_;
    const int* maskg = mask + (size_t)b * S_ * S_ + (size_t)(qblk * 256) * S_;
    const int* mfl = g_mflag + (b * 8 + qblk) * 32;

    const int r0 = warp * 32 + grp;

    {
        float* Qs = (float*)Mi;
#pragma unroll
        for (int p = 0; p < 16; p++) {
            int idx = p * 256 + tid;
            int r = idx >> 4;
            int c = (idx & 15) * 4;
            *(float4*)&Qs[r * AMS + c] = *(const float4*)(Qg + (size_t)r * 64 + c);
        }
    }
    __syncthreads();

    uint32_t qa[2][4][4];
    {
        const float* Qs = (const float*)Mi;
#pragma unroll
        for (int mf = 0; mf < 2; mf++) {
            int ra = r0 + mf * 16, rb = ra + 8;
#pragma unroll
            for (int kc = 0; kc < 4; kc++) {
                int c = kc * 16 + 2 * t4;
                qa[mf][kc][0] = f16pk(Qs[ra * AMS + c],     Qs[ra * AMS + c + 1]);
                qa[mf][kc][1] = f16pk(Qs[rb * AMS + c],     Qs[rb * AMS + c + 1]);
                qa[mf][kc][2] = f16pk(Qs[ra * AMS + c + 8], Qs[ra * AMS + c + 9]);
                qa[mf][kc][3] = f16pk(Qs[rb * AMS + c + 8], Qs[rb * AMS + c + 9]);
            }
        }
    }
    __syncthreads();

    float o[2][8][4];
#pragma unroll
    for (int mf = 0; mf < 2; mf++)
#pragma unroll
        for (int nf = 0; nf < 8; nf++)
#pragma unroll
            for (int i = 0; i < 4; i++) o[mf][nf][i] = 0.f;

    float mrow[4] = {-1e30f, -1e30f, -1e30f, -1e30f};
    float lrow[4] = {0.f, 0.f, 0.f, 0.f};

    const int kr_r = tid >> 4;
    const int kr_c = (tid & 15) * 4;

    float4 kr[4], vra[2], vrb[2];
#pragma unroll
    for (int p = 0; p < 4; p++)
        kr[p] = *(const float4*)(Kg + (size_t)(p * 16 + kr_r) * 64 + kr_c);
#pragma unroll
    for (int p = 0; p < 2; p++) {
        int pr = p * 16 + kr_r;
        vra[p] = *(const float4*)(Vg + (size_t)(2 * pr) * 64 + kr_c);
        vrb[p] = *(const float4*)(Vg + (size_t)(2 * pr + 1) * 64 + kr_c);
    }

    for (int t = 0; t < 32; t++) {
        const int allones = mfl[t];
        if (t) __syncthreads();

#pragma unroll
        for (int p = 0; p < 4; p++) {
            int r = p * 16 + kr_r;
            *(uint2*)&Kpk[r * KPS + (kr_c >> 1)] =
                make_uint2(f16pk(kr[p].x, kr[p].y), f16pk(kr[p].z, kr[p].w));
        }
#pragma unroll
        for (int p = 0; p < 2; p++) {
            int pr = p * 16 + kr_r;
            *(uint4*)&Vpk[pr * VPS + kr_c] =
                make_uint4(f16pk(vra[p].x, vrb[p].x), f16pk(vra[p].y, vrb[p].y),
                           f16pk(vra[p].z, vrb[p].z), f16pk(vra[p].w, vrb[p].w));
        }
        if (!allones) {
#pragma unroll
            for (int p = 0; p < 16; p++) {
                int idx = p * 256 + tid;
                int r = idx >> 4;
                int c4 = (idx & 15) * 4;
                uint32_t dst = (uint32_t)__cvta_generic_to_shared(&Mi[r * AMS + c4]);
                cp_async16(dst, maskg + (size_t)r * S_ + t * 64 + c4);
            }
            asm volatile("cp.async.commit_group;");
        }
        __syncthreads();

        float sc[2][8][4];
#pragma unroll
        for (int nf = 0; nf < 8; nf++) {
#pragma unroll
            for (int i = 0; i < 4; i++) { sc[0][nf][i] = 0.f; sc[1][nf][i] = 0.f; }
#pragma unroll
            for (int kc = 0; kc < 4; kc++) {
                uint32_t b0 = Kpk[(nf * 8 + grp) * KPS + kc * 8 + t4];
                uint32_t b1 = Kpk[(nf * 8 + grp) * KPS + kc * 8 + 4 + t4];
                mma_fp16(sc[0][nf], qa[0][kc], b0, b1);
                mma_fp16(sc[1][nf], qa[1][kc], b0, b1);
            }
        }

        if (!allones) {
            asm volatile("cp.async.wait_group 0;");
            __syncthreads();
        }

#pragma unroll
        for (int mf = 0; mf < 2; mf++) {
            int ra = r0 + mf * 16, rb = ra + 8;
            if (!allones) {
#pragma unroll
                for (int nf = 0; nf < 8; nf++) {
                    int2 ma = *(const int2*)&Mi[ra * AMS + nf * 8 + 2 * t4];
                    int2 mb = *(const int2*)&Mi[rb * AMS + nf * 8 + 2 * t4];
                    if (ma.x == 0) sc[mf][nf][0] = -1e9f;
                    if (ma.y == 0) sc[mf][nf][1] = -1e9f;
                    if (mb.x == 0) sc[mf][nf][2] = -1e9f;
                    if (mb.y == 0) sc[mf][nf][3] = -1e9f;
                }
            }
            float tma = -1e30f, tmb = -1e30f;
#pragma unroll
            for (int nf = 0; nf < 8; nf++) {
                tma = fmaxf(tma, fmaxf(sc[mf][nf][0], sc[mf][nf][1]));
                tmb = fmaxf(tmb, fmaxf(sc[mf][nf][2], sc[mf][nf][3]));
            }
            tma = fmaxf(tma, __shfl_xor_sync(0xffffffffu, tma, 1));
            tma = fmaxf(tma, __shfl_xor_sync(0xffffffffu, tma, 2));
            tmb = fmaxf(tmb, __shfl_xor_sync(0xffffffffu, tmb, 1));
            tmb = fmaxf(tmb, __shfl_xor_sync(0xffffffffu, tmb, 2));

            float mna = fmaxf(mrow[2 * mf], tma);
            float mnb = fmaxf(mrow[2 * mf + 1], tmb);
            float ala = __expf(mrow[2 * mf] - mna);
            float alb = __expf(mrow[2 * mf + 1] - mnb);
            mrow[2 * mf] = mna; mrow[2 * mf + 1] = mnb;

            float rsa = 0.f, rsb = 0.f;
#pragma unroll
            for (int nf = 0; nf < 8; nf++) {
                float p00 = __expf(sc[mf][nf][0] - mna);
                float p01 = __expf(sc[mf][nf][1] - mna);
                float p10 = __expf(sc[mf][nf][2] - mnb);
                float p11 = __expf(sc[mf][nf][3] - mnb);
                rsa += p00 + p01;
                rsb += p10 + p11;
                Ppk[ra * PPS + nf * 4 + t4] = f16pk(p00, p01);
                Ppk[rb * PPS + nf * 4 + t4] = f16pk(p10, p11);
                o[mf][nf][0] *= ala; o[mf][nf][1] *= ala;
                o[mf][nf][2] *= alb; o[mf][nf][3] *= alb;
            }
            rsa += __shfl_xor_sync(0xffffffffu, rsa, 1);
            rsa += __shfl_xor_sync(0xffffffffu, rsa, 2);
            rsb += __shfl_xor_sync(0xffffffffu, rsb, 1);
            rsb += __shfl_xor_sync(0xffffffffu, rsb, 2);
            lrow[2 * mf]     = lrow[2 * mf] * ala + rsa;
            lrow[2 * mf + 1] = lrow[2 * mf + 1] * alb + rsb;
        }
        __syncwarp();

        if (t < 31) {
            const float* Kn = Kg + (size_t)(t + 1) * 64 * 64;
            const float* Vn = Vg + (size_t)(t + 1) * 64 * 64;
#pragma unroll
            for (int p = 0; p < 4; p++)
                kr[p] = *(const float4*)(Kn + (size_t)(p * 16 + kr_r) * 64 + kr_c);
#pragma unroll
            for (int p = 0; p < 2; p++) {
                int pr = p * 16 + kr_r;
                vra[p] = *(const float4*)(Vn + (size_t)(2 * pr) * 64 + kr_c);
                vrb[p] = *(const float4*)(Vn + (size_t)(2 * pr + 1) * 64 + kr_c);
            }
        }

#pragma unroll
        for (int kc = 0; kc < 4; kc++) {
            uint32_t pa[2][4];
#pragma unroll
            for (int mf = 0; mf < 2; mf++) {
                int ra = r0 + mf * 16, rb = ra + 8;
                pa[mf][0] = Ppk[ra * PPS + kc * 8 + t4];
                pa[mf][1] = Ppk[rb * PPS + kc * 8 + t4];
                pa[mf][2] = Ppk[ra * PPS + kc * 8 + 4 + t4];
                pa[mf][3] = Ppk[rb * PPS + kc * 8 + 4 + t4];
            }
#pragma unroll
            for (int nf = 0; nf < 8; nf++) {
                uint32_t b0 = Vpk[(kc * 8 + t4) * VPS + nf * 8 + grp];
                uint32_t b1 = Vpk[(kc * 8 + 4 + t4) * VPS + nf * 8 + grp];
                mma_fp16(o[0][nf], pa[0], b0, b1);
                mma_fp16(o[1][nf], pa[1], b0, b1);
            }
        }
    }

#pragma unroll
    for (int mf = 0; mf < 2; mf++) {
        float inva = 1.f / lrow[2 * mf];
        float invb = 1.f / lrow[2 * mf + 1];
        int ga = qblk * 256 + r0 + mf * 16;
        int gb = ga + 8;
        float* opa = out + ((size_t)b * S_ + ga) * D_ + h * 64;
        float* opb = out + ((size_t)b * S_ + gb) * D_ + h * 64;
#pragma unroll
        for (int nf = 0; nf < 8; nf++) {
            int cb = nf * 8 + 2 * t4;
            *(float2*)(opa + cb) = make_float2(o[mf][nf][0] * inva, o[mf][nf][1] * inva);
            *(float2*)(opb + cb) = make_float2(o[mf][nf][2] * invb, o[mf][nf][3] * invb);
        }
    }
}

// ---------------------------------------------------------------------------
// Launch
// Inputs (metadata order): query, key, value, mask, Wq, bq, Wk, bk, Wv, bv
// ---------------------------------------------------------------------------
extern "C" void kernel_launch(void* const* d_in, const int* in_sizes, int n_in,
                              void* d_out, int out_size)
{
    const float* query = (const float*)d_in[0];
    const float* key   = (const float*)d_in[1];
    const float* value = (const float*)d_in[2];
    const int*   mask  = (const int*)  d_in[3];
    const float* Wq    = (const float*)d_in[4];
    const float* bq    = (const float*)d_in[5];
    const float* Wk    = (const float*)d_in[6];
    const float* bk    = (const float*)d_in[7];
    const float* Wv    = (const float*)d_in[8];
    const float* bv    = (const float*)d_in[9];
    float* out = (float*)d_out;

    float *qptr, *kptr, *vptr;
    cudaGetSymbolAddress((void**)&qptr, g_Q);
    cudaGetSymbolAddress((void**)&kptr, g_K);
    cudaGetSymbolAddress((void**)&vptr, g_V);

    // prep: fp32 -> packed fp16 planes
    prep_x<<<dim3(8192, 1, 3), 256>>>(query, key, value);
    prep_w<<<dim3(1024, 1, 3), 256>>>(Wq, Wk, Wv);
    mask_scan<<<dim3(32, 8, 4), 256>>>(mask);

    // fused projections (fp16 single-pass)
    const int psmem = 2 * BUFW * (int)sizeof(uint32_t);   // 73,728 B
    cudaFuncSetAttribute(proj_gemm, cudaFuncAttributeMaxDynamicSharedMemorySize, psmem);
    proj_gemm<<<dim3(8, 64, 3), 256, psmem>>>(bq, bk, bv, qptr, kptr, vptr);

    // attention
    const int asmem = (64 * KPS + 32 * VPS + 256 * PPS + 256 * AMS) * (int)sizeof(uint32_t);
    cudaFuncSetAttribute(attn_mma, cudaFuncAttributeMaxDynamicSharedMemorySize, asmem);
    attn_mma<<<dim3(8, 64), 256, asmem>>>(mask, out);
}

// round 10
// speedup vs baseline: 23.8889x; 1.0104x over previous
#include <cuda_runtime.h>
#include <cuda_fp16.h>
#include <cstdint>
#include <math.h>

// Problem constants
#define B_  4
#define S_  2048
#define D_  1024
#define H_  16
#define DK_ 64

// Scratch (device globals — no allocs)
__device__ int g_mflag[B_ * 8 * 32];
// pre-converted fp16 planes (packed pairs along k: one word = 2 fp16)
__device__ uint32_t g_Xpk[(size_t)3 * 8192 * 512];
__device__ uint32_t g_Wpk[(size_t)3 * 1024 * 512];
// projected Q/K/V, packed fp16 [bh][s][32 words]; Q pre-scaled by 0.125
__device__ uint32_t g_Qh[(size_t)64 * 2048 * 32];
__device__ uint32_t g_Kh[(size_t)64 * 2048 * 32];
__device__ uint32_t g_Vh[(size_t)64 * 2048 * 32];

// ---------------------------------------------------------------------------
// helpers
// ---------------------------------------------------------------------------
__device__ __forceinline__ uint32_t f16pk(float x0, float x1) {
    __half2 h = __floats2half2_rn(x0, x1);
    return *(uint32_t*)&h;
}

__device__ __forceinline__ void mma_fp16(float* d, const uint32_t* a,
                                         uint32_t b0, uint32_t b1)
{
    asm volatile(
        "mma.sync.aligned.m16n8k16.row.col.f32.f16.f16.f32 "
        "{%0,%1,%2,%3},{%4,%5,%6,%7},{%8,%9},{%0,%1,%2,%3};"
        : "+f"(d[0]), "+f"(d[1]), "+f"(d[2]), "+f"(d[3])
        : "r"(a[0]), "r"(a[1]), "r"(a[2]), "r"(a[3]), "r"(b0), "r"(b1));
}

__device__ __forceinline__ void cp_async16(uint32_t dst_smem, const void* src) {
    asm volatile("cp.async.cg.shared.global [%0], [%1], 16;"
                 :: "r"(dst_smem), "l"(src));
}

__device__ __forceinline__ void ldsm_x2(uint32_t& r0, uint32_t& r1, uint32_t addr) {
    asm volatile("ldmatrix.sync.aligned.m8n8.x2.shared.b16 {%0,%1}, [%2];"
                 : "=r"(r0), "=r"(r1) : "r"(addr));
}

__device__ __forceinline__ void ldsm_x2_trans(uint32_t& r0, uint32_t& r1, uint32_t addr) {
    asm volatile("ldmatrix.sync.aligned.m8n8.x2.trans.shared.b16 {%0,%1}, [%2];"
                 : "=r"(r0), "=r"(r1) : "r"(addr));
}

// ---------------------------------------------------------------------------
// Prep: fp32 -> packed fp16 planes (unchanged, proven)
// ---------------------------------------------------------------------------
__global__ __launch_bounds__(256)
void prep_x(const float* __restrict__ q, const float* __restrict__ k,
            const float* __restrict__ v)
{
    const int z = blockIdx.z;
    const int m = blockIdx.x;
    const int kq = threadIdx.x;
    const float* src = (z == 0) ? q : (z == 1) ? k : v;
    float4 xv = *((const float4*)(src + (size_t)m * 1024) + kq);
    size_t w = ((size_t)z * 8192 + m) * 512 + kq * 2;
    *(uint2*)&g_Xpk[w] = make_uint2(f16pk(xv.x, xv.y), f16pk(xv.z, xv.w));
}

__global__ __launch_bounds__(256)
void prep_w(const float* __restrict__ wq, const float* __restrict__ wk,
            const float* __restrict__ wv)
{
    const int z = blockIdx.z;
    const int n = blockIdx.x;
    const int kq = threadIdx.x;
    const float* src = (z == 0) ? wq : (z == 1) ? wk : wv;
    float4 xv = *((const float4*)(src + (size_t)n * 1024) + kq);
    size_t w = ((size_t)z * 1024 + n) * 512 + kq * 2;
    *(uint2*)&g_Wpk[w] = make_uint2(f16pk(xv.x, xv.y), f16pk(xv.z, xv.w));
}

// ---------------------------------------------------------------------------
// Fused projection GEMM, fp16 m16n8k16 (fp32 accum), cp.async double buffered.
// Mainloop identical to round 9 (proven). Epilogue writes packed fp16
// directly into g_Qh/g_Kh/g_Vh (identical rounding to previous staging).
// ---------------------------------------------------------------------------
#define PST 36
#define PLW (128 * PST)
#define BUFW (2 * PLW)

__global__ __launch_bounds__(256, 2)
void proj_gemm(const float* __restrict__ bq, const float* __restrict__ bk,
               const float* __restrict__ bv)
{
    extern __shared__ uint32_t sbuf[];

    const int tid  = threadIdx.x;
    const int warp = tid >> 5;
    const int lane = tid & 31;
    const int grp  = lane >> 2;
    const int t4   = lane & 3;
    const int bm   = blockIdx.y;
    const int bn   = blockIdx.x;
    const int z    = blockIdx.z;
    const int wm   = (warp >> 2) * 64;
    const int wn   = (warp & 3) * 32;

    const float* bias = (z == 0) ? bq : (z == 1) ? bk : bv;
    uint32_t* outh    = (z == 0) ? g_Qh : (z == 1) ? g_Kh : g_Vh;
    const bool scale  = (z == 0);

    const uint32_t* xpk = g_Xpk + ((size_t)z * 8192 + bm * 128) * 512;
    const uint32_t* wpk = g_Wpk + ((size_t)z * 1024 + bn * 128) * 512;

    auto issue = [&](int kt, int sel) {
        uint32_t* dst = sbuf + sel * BUFW;
#pragma unroll
        for (int q = 0; q < 4; q++) {
            int idx = q * 256 + tid;
            int r = idx >> 3;
            int g4 = (idx & 7) * 4;
            uint32_t dA = (uint32_t)__cvta_generic_to_shared(dst + r * PST + g4);
            uint32_t dB = (uint32_t)__cvta_generic_to_shared(dst + PLW + r * PST + g4);
            cp_async16(dA, xpk + (size_t)r * 512 + kt * 32 + g4);
            cp_async16(dB, wpk + (size_t)r * 512 + kt * 32 + g4);
        }
        asm volatile("cp.async.commit_group;");
    };

    float acc[4][4][4];
#pragma unroll
    for (int mf = 0; mf < 4; mf++)
#pragma unroll
        for (int nf = 0; nf < 4; nf++)
#pragma unroll
            for (int i = 0; i < 4; i++) acc[mf][nf][i] = 0.f;

    issue(0, 0);

    for (int ks = 0; ks < 16; ks++) {
        const uint32_t* cur = sbuf + (ks & 1) * BUFW;
        if (ks < 15) {
            issue(ks + 1, (ks + 1) & 1);
            asm volatile("cp.async.wait_group 1;");
        } else {
            asm volatile("cp.async.wait_group 0;");
        }
        __syncthreads();

        const uint32_t* sA = cur;
        const uint32_t* sB = cur + PLW;

#pragma unroll
        for (int kc = 0; kc < 4; kc++) {
            const int kp = kc * 8 + t4;
            uint32_t ah[4][4];
#pragma unroll
            for (int mf = 0; mf < 4; mf++) {
                int r0 = wm + mf * 16 + grp;
                ah[mf][0] = sA[r0 * PST + kp];
                ah[mf][1] = sA[(r0 + 8) * PST + kp];
                ah[mf][2] = sA[r0 * PST + kp + 4];
                ah[mf][3] = sA[(r0 + 8) * PST + kp + 4];
            }
#pragma unroll
            for (int nf = 0; nf < 4; nf++) {
                int n = wn + nf * 8 + grp;
                uint32_t b0 = sB[n * PST + kp];
                uint32_t b1 = sB[n * PST + kp + 4];
#pragma unroll
                for (int mf = 0; mf < 4; mf++)
                    mma_fp16(acc[mf][nf], ah[mf], b0, b1);
            }
        }
        __syncthreads();
    }

    // Epilogue: bias, optional scale, pack fp16, scatter into [bh][s][32 words]
#pragma unroll
    for (int mf = 0; mf < 4; mf++) {
        int row0 = bm * 128 + wm + mf * 16 + grp;
        int row1 = row0 + 8;
        int b0i = row0 >> 11, s0 = row0 & 2047;
        int b1i = row1 >> 11, s1 = row1 & 2047;
#pragma unroll
        for (int nf = 0; nf < 4; nf++) {
            int col = bn * 128 + wn + nf * 8 + 2 * t4;
            int h  = col >> 6;
            int wi = (col & 63) >> 1;
            float bb0 = bias[col], bb1 = bias[col + 1];
            float v00 = acc[mf][nf][0] + bb0;
            float v01 = acc[mf][nf][1] + bb1;
            float v10 = acc[mf][nf][2] + bb0;
            float v11 = acc[mf][nf][3] + bb1;
            if (scale) { v00 *= 0.125f; v01 *= 0.125f; v10 *= 0.125f; v11 *= 0.125f; }
            outh[((size_t)(b0i * 16 + h) * 2048 + s0) * 32 + wi] = f16pk(v00, v01);
            outh[((size_t)(b1i * 16 + h) * 2048 + s1) * 32 + wi] = f16pk(v10, v11);
        }
    }
}

// ---------------------------------------------------------------------------
// Mask scan (unchanged)
// ---------------------------------------------------------------------------
__global__ void mask_scan(const int* __restrict__ mask)
{
    const int kt = blockIdx.x;
    const int qt = blockIdx.y;
    const int b  = blockIdx.z;
    const int* rp = mask + ((size_t)b * S_ + qt * 256 + threadIdx.x) * S_ + kt * 64;
    int ok = 1;
#pragma unroll
    for (int c = 0; c < 64; c += 4) {
        int4 v = *(const int4*)(rp + c);
        ok &= (v.x != 0) & (v.y != 0) & (v.z != 0) & (v.w != 0);
    }
    ok = __syncthreads_and(ok);
    if (threadIdx.x == 0) g_mflag[(b * 8 + qt) * 32 + kt] = ok;
}

// ---------------------------------------------------------------------------
// Flash attention, FP16, mf=1, 512 threads (16 warps, 4/SMSP).
// CTA: 256-row q-tile; warp owns 16 q-rows (rows ra=warp*16+grp, rb=ra+8).
// K/V fp16 tiles via cp.async double buffer (stride 144B); B-frags via
// ldmatrix.x2 (K non-trans, V trans). Q frags: one-time direct LDG.
// Mask: direct LDG in the (never-taken here) masked path.
// smem: KV bufs 2 x (64x36 K + 64x36 V) + P 256x36 = 18432 words = 72KB.
// ---------------------------------------------------------------------------
#define KVS 36
#define KVB (2 * 64 * KVS)     // words per KV buffer (K then V)

__global__ __launch_bounds__(512, 1)
void attn_mma(const int* __restrict__ mask, float* __restrict__ out)
{
    extern __shared__ uint32_t smu[];
    uint32_t* Pp = smu + 2 * KVB;          // 256*36 words

    const int tid  = threadIdx.x;
    const int warp = tid >> 5;     // 0..15
    const int lane = tid & 31;
    const int grp  = lane >> 2;
    const int t4   = lane & 3;

    const int qblk = blockIdx.x;   // 0..7
    const int bh   = blockIdx.y;   // 0..63
    const int b    = bh >> 4;
    const int h    = bh & 15;

    const uint32_t* Qh = g_Qh + ((size_t)bh * 2048 + qblk * 256) * 32;
    const uint32_t* Kh = g_Kh + (size_t)bh * 2048 * 32;
    const uint32_t* Vh = g_Vh + (size_t)bh * 2048 * 32;
    const int* maskg = mask + (size_t)b * S_ * S_ + (size_t)(qblk * 256) * S_;
    const int* mfl = g_mflag + (b * 8 + qblk) * 32;

    const int ra = warp * 16 + grp;
    const int rb = ra + 8;

    const uint32_t smb = (uint32_t)__cvta_generic_to_shared(smu);
    // per-lane ldmatrix base offsets (bytes)
    const uint32_t kb_l = (lane & 7) * (KVS * 4) + ((lane >> 3) & 1) * 16;
    const uint32_t vb_l = (lane & 15) * (KVS * 4);

    // ---- Q fragments: direct LDG (one time) ----
    uint32_t qa[4][4];
#pragma unroll
    for (int kc = 0; kc < 4; kc++) {
        qa[kc][0] = Qh[(size_t)ra * 32 + kc * 8 + t4];
        qa[kc][1] = Qh[(size_t)rb * 32 + kc * 8 + t4];
        qa[kc][2] = Qh[(size_t)ra * 32 + kc * 8 + 4 + t4];
        qa[kc][3] = Qh[(size_t)rb * 32 + kc * 8 + 4 + t4];
    }

    float o[8][4];
#pragma unroll
    for (int nf = 0; nf < 8; nf++)
#pragma unroll
        for (int i = 0; i < 4; i++) o[nf][i] = 0.f;

    float m0 = -1e30f, m1 = -1e30f, l0 = 0.f, l1 = 0.f;

    // stage K/V tile t into buffer sel: 512 chunks each (1 cp.async/thread each)
    auto stage = [&](int t, int sel) {
        uint32_t* dst = smu + sel * KVB;
        int r = tid >> 3, c4 = (tid & 7) * 4;
        uint32_t dK = (uint32_t)__cvta_generic_to_shared(dst + r * KVS + c4);
        uint32_t dV = (uint32_t)__cvta_generic_to_shared(dst + 64 * KVS + r * KVS + c4);
        cp_async16(dK, Kh + (size_t)(t * 64 + r) * 32 + c4);
        cp_async16(dV, Vh + (size_t)(t * 64 + r) * 32 + c4);
        asm volatile("cp.async.commit_group;");
    };

    stage(0, 0);

    for (int t = 0; t < 32; t++) {
        const int allones = mfl[t];
        if (t < 31) {
            __syncthreads();               // all warps done reading buf[(t+1)&1]
            stage(t + 1, (t + 1) & 1);
            asm volatile("cp.async.wait_group 1;");
        } else {
            asm volatile("cp.async.wait_group 0;");
        }
        __syncthreads();

        const uint32_t Kt = smb + (t & 1) * (KVB * 4);
        const uint32_t Vt = Kt + 64 * KVS * 4;

        // ---- QK: B-frags via ldmatrix.x2 from K tile ----
        float sc[8][4];
#pragma unroll
        for (int nf = 0; nf < 8; nf++) {
#pragma unroll
            for (int i = 0; i < 4; i++) sc[nf][i] = 0.f;
#pragma unroll
            for (int kc = 0; kc < 4; kc++) {
                uint32_t b0, b1;
                ldsm_x2(b0, b1, Kt + kb_l + nf * (8 * KVS * 4) + kc * 32);
                mma_fp16(sc[nf], qa[kc], b0, b1);
            }
        }

        // ---- mask (register path; only when tile has zeros) ----
        if (!allones) {
#pragma unroll
            for (int nf = 0; nf < 8; nf++) {
                int kcol = t * 64 + nf * 8 + 2 * t4;
                int2 ma = *(const int2*)(maskg + (size_t)ra * S_ + kcol);
                int2 mb = *(const int2*)(maskg + (size_t)rb * S_ + kcol);
                if (ma.x == 0) sc[nf][0] = -1e9f;
                if (ma.y == 0) sc[nf][1] = -1e9f;
                if (mb.x == 0) sc[nf][2] = -1e9f;
                if (mb.y == 0) sc[nf][3] = -1e9f;
            }
        }

        // ---- online softmax (rows ra, rb) ----
        float tma = -1e30f, tmb = -1e30f;
#pragma unroll
        for (int nf = 0; nf < 8; nf++) {
            tma = fmaxf(tma, fmaxf(sc[nf][0], sc[nf][1]));
            tmb = fmaxf(tmb, fmaxf(sc[nf][2], sc[nf][3]));
        }
        tma = fmaxf(tma, __shfl_xor_sync(0xffffffffu, tma, 1));
        tma = fmaxf(tma, __shfl_xor_sync(0xffffffffu, tma, 2));
        tmb = fmaxf(tmb, __shfl_xor_sync(0xffffffffu, tmb, 1));
        tmb = fmaxf(tmb, __shfl_xor_sync(0xffffffffu, tmb, 2));

        float mn0 = fmaxf(m0, tma);
        float mn1 = fmaxf(m1, tmb);
        float al0 = __expf(m0 - mn0);
        float al1 = __expf(m1 - mn1);
        m0 = mn0; m1 = mn1;

        float rs0 = 0.f, rs1 = 0.f;
#pragma unroll
        for (int nf = 0; nf < 8; nf++) {
            float p00 = __expf(sc[nf][0] - mn0);
            float p01 = __expf(sc[nf][1] - mn0);
            float p10 = __expf(sc[nf][2] - mn1);
            float p11 = __expf(sc[nf][3] - mn1);
            rs0 += p00 + p01;
            rs1 += p10 + p11;
            Pp[ra * KVS + nf * 4 + t4] = f16pk(p00, p01);
            Pp[rb * KVS + nf * 4 + t4] = f16pk(p10, p11);
            o[nf][0] *= al0; o[nf][1] *= al0;
            o[nf][2] *= al1; o[nf][3] *= al1;
        }
        rs0 += __shfl_xor_sync(0xffffffffu, rs0, 1);
        rs0 += __shfl_xor_sync(0xffffffffu, rs0, 2);
        rs1 += __shfl_xor_sync(0xffffffffu, rs1, 1);
        rs1 += __shfl_xor_sync(0xffffffffu, rs1, 2);
        l0 = l0 * al0 + rs0;
        l1 = l1 * al1 + rs1;

        __syncwarp();   // P round-trip is warp-local

        // ---- PV: A from P (LDS), B via ldmatrix.x2.trans from V tile ----
#pragma unroll
        for (int kc = 0; kc < 4; kc++) {
            uint32_t pa[4];
            pa[0] = Pp[ra * KVS + kc * 8 + t4];
            pa[1] = Pp[rb * KVS + kc * 8 + t4];
            pa[2] = Pp[ra * KVS + kc * 8 + 4 + t4];
            pa[3] = Pp[rb * KVS + kc * 8 + 4 + t4];
#pragma unroll
            for (int nf = 0; nf < 8; nf++) {
                uint32_t b0, b1;
                ldsm_x2_trans(b0, b1, Vt + vb_l + kc * (16 * KVS * 4) + nf * 16);
                mma_fp16(o[nf], pa, b0, b1);
            }
        }
    }

    // ---- finalize: O / l, write [B,S,D] ----
    float inv0 = 1.f / l0;
    float inv1 = 1.f / l1;
    int ga = qblk * 256 + ra;
    int gb = ga + 8;
    float* opa = out + ((size_t)b * S_ + ga) * D_ + h * 64;
    float* opb = out + ((size_t)b * S_ + gb) * D_ + h * 64;
#pragma unroll
    for (int nf = 0; nf < 8; nf++) {
        int cb = nf * 8 + 2 * t4;
        *(float2*)(opa + cb) = make_float2(o[nf][0] * inv0, o[nf][1] * inv0);
        *(float2*)(opb + cb) = make_float2(o[nf][2] * inv1, o[nf][3] * inv1);
    }
}

// ---------------------------------------------------------------------------
// Launch
// Inputs (metadata order): query, key, value, mask, Wq, bq, Wk, bk, Wv, bv
// ---------------------------------------------------------------------------
extern "C" void kernel_launch(void* const* d_in, const int* in_sizes, int n_in,
                              void* d_out, int out_size)
{
    const float* query = (const float*)d_in[0];
    const float* key   = (const float*)d_in[1];
    const float* value = (const float*)d_in[2];
    const int*   mask  = (const int*)  d_in[3];
    const float* Wq    = (const float*)d_in[4];
    const float* bq    = (const float*)d_in[5];
    const float* Wk    = (const float*)d_in[6];
    const float* bk    = (const float*)d_in[7];
    const float* Wv    = (const float*)d_in[8];
    const float* bv    = (const float*)d_in[9];
    float* out = (float*)d_out;

    // prep: fp32 -> packed fp16 planes
    prep_x<<<dim3(8192, 1, 3), 256>>>(query, key, value);
    prep_w<<<dim3(1024, 1, 3), 256>>>(Wq, Wk, Wv);
    mask_scan<<<dim3(32, 8, 4), 256>>>(mask);

    // fused projections (fp16 single-pass, fp16 outputs)
    const int psmem = 2 * BUFW * (int)sizeof(uint32_t);   // 73,728 B
    cudaFuncSetAttribute(proj_gemm, cudaFuncAttributeMaxDynamicSharedMemorySize, psmem);
    proj_gemm<<<dim3(8, 64, 3), 256, psmem>>>(bq, bk, bv);

    // attention: 512 threads, 16 warps, mf=1
    const int asmem = (2 * KVB + 256 * KVS) * (int)sizeof(uint32_t);   // 73,728 B
    cudaFuncSetAttribute(attn_mma, cudaFuncAttributeMaxDynamicSharedMemorySize, asmem);
    attn_mma<<<dim3(8, 64), 512, asmem>>>(mask, out);
}